// round 13
// baseline (speedup 1.0000x reference)
#include <cuda_runtime.h>
#include <cuda_bf16.h>
#include <math.h>
#include <stdint.h>

// ---------------- problem constants ----------------
constexpr int kD   = 1024;
constexpr int kHD  = 64;
constexpr int kNH  = 16;
constexpr int kH   = 16;   // routing heads
constexpr int kKH  = 8;
constexpr int kN   = 128;  // tokens per block
constexpr int kE   = 4096;
constexpr int kRE  = 4;
constexpr int kDE  = 4;
constexpr int kET  = 16;   // RE*DE
constexpr int kS   = 2048;
constexpr int kT   = 2048;
constexpr int kBC  = 16;   // T / N
constexpr float kEPS   = 1e-5f;
constexpr float kTHETA = 10000.0f;

// ---------------- device scratch ----------------
__device__ float g_qkv  [kT * 3 * kD];    // qkv
__device__ float g_proj [kT * kD];        // attn out-proj
__device__ float g_resid[kT * kD];        // x_ffn_input
__device__ float g_xf   [kT * kD];        // rmsnorm(x_ffn_input)
__device__ float g_G    [kT * kET * 8];   // gathered routing dots per (t, j, h2)
__device__ float g_w    [kT * kET];       // combined gate weights
// split-bf16 buffers for tensor-core GEMMs / attention
__device__ __nv_bfloat16 g_xnh[kT * kD];          // rmsnorm(x) hi
__device__ __nv_bfloat16 g_xnl[kT * kD];          // rmsnorm(x) lo
__device__ __nv_bfloat16 g_w1h[3 * kD * kD];      // attn_w transposed [3D][D] hi
__device__ __nv_bfloat16 g_w1l[3 * kD * kD];
__device__ __nv_bfloat16 g_w2h[kD * kD];          // attn_out_w transposed hi
__device__ __nv_bfloat16 g_w2l[kD * kD];
__device__ __nv_bfloat16 g_ah [kT * kD];          // attention output hi
__device__ __nv_bfloat16 g_al [kT * kD];          // attention output lo
__device__ __nv_bfloat16 g_qh [kNH * kS * kHD];   // rope'd q bf16, (h,s,d)
__device__ __nv_bfloat16 g_kh [kNH * kS * kHD];   // rope'd k bf16
__device__ __nv_bfloat16 g_vh [kNH * kS * kHD];   // v hi, (h,s,d)
__device__ __nv_bfloat16 g_vl [kNH * kS * kHD];   // v lo

// ---------------- helpers ----------------
__device__ __forceinline__ float block_reduce_sum_256(float v) {
    __shared__ float red[8];
    #pragma unroll
    for (int o = 16; o; o >>= 1) v += __shfl_xor_sync(0xffffffffu, v, o);
    if ((threadIdx.x & 31) == 0) red[threadIdx.x >> 5] = v;
    __syncthreads();
    float s = 0.f;
    #pragma unroll
    for (int i = 0; i < 8; i++) s += red[i];
    __syncthreads();
    return s;
}

// exp(x) for |x| <= 0.13 : degree-4 Taylor, abs err ~3e-7, 4 FMA, no MUFU.
__device__ __forceinline__ float exp_small(float x) {
    float e = fmaf(x, 1.0f / 24.0f, 1.0f / 6.0f);
    e = fmaf(e, x, 0.5f);
    e = fmaf(e, x, 1.0f);
    e = fmaf(e, x, 1.0f);
    return e;
}

__device__ __forceinline__ __nv_bfloat162 split_pair(float a, float b,
                                                     __nv_bfloat162& lo) {
    __nv_bfloat16 ha = __float2bfloat16(a);
    __nv_bfloat16 hb = __float2bfloat16(b);
    lo = __nv_bfloat162(__float2bfloat16(a - __bfloat162float(ha)),
                        __float2bfloat16(b - __bfloat162float(hb)));
    return __nv_bfloat162(ha, hb);
}

__device__ __forceinline__ uint32_t smem_u32(const void* p) {
    uint32_t a;
    asm("{ .reg .u64 t; cvta.to.shared.u64 t, %1; cvt.u32.u64 %0, t; }" : "=r"(a) : "l"(p));
    return a;
}

__device__ __forceinline__ uint32_t sw128(uint32_t off) {
    return off ^ ((off >> 3) & 0x70);
}
__device__ __forceinline__ uint32_t sw64(uint32_t off) {
    return off ^ ((off >> 3) & 0x30);
}
__device__ __forceinline__ void ldsm4(uint32_t* d, uint32_t a) {
    asm volatile("ldmatrix.sync.aligned.m8n8.x4.shared.b16 {%0,%1,%2,%3}, [%4];"
        : "=r"(d[0]), "=r"(d[1]), "=r"(d[2]), "=r"(d[3]) : "r"(a));
}
__device__ __forceinline__ void ldsm4t(uint32_t* d, uint32_t a) {
    asm volatile("ldmatrix.sync.aligned.m8n8.x4.trans.shared.b16 {%0,%1,%2,%3}, [%4];"
        : "=r"(d[0]), "=r"(d[1]), "=r"(d[2]), "=r"(d[3]) : "r"(a));
}
__device__ __forceinline__ void hmma(float* d, const uint32_t* a, const uint32_t* b) {
    asm volatile("mma.sync.aligned.m16n8k16.row.col.f32.bf16.bf16.f32 "
        "{%0,%1,%2,%3}, {%4,%5,%6,%7}, {%8,%9}, {%0,%1,%2,%3};"
        : "+f"(d[0]), "+f"(d[1]), "+f"(d[2]), "+f"(d[3])
        : "r"(a[0]), "r"(a[1]), "r"(a[2]), "r"(a[3]), "r"(b[0]), "r"(b[1]));
}
__device__ __forceinline__ void cp_async16(uint32_t dst, const void* src) {
    asm volatile("cp.async.cg.shared.global [%0], [%1], 16;" :: "r"(dst), "l"(src) : "memory");
}
__device__ __forceinline__ void cp_commit() {
    asm volatile("cp.async.commit_group;" ::: "memory");
}

// ---------------- K1: rmsnorm -> split bf16 hi/lo ----------------
__global__ void rmsnorm_bf16_kernel(const float* __restrict__ x,
                                    const float* __restrict__ w,
                                    __nv_bfloat16* __restrict__ oh,
                                    __nv_bfloat16* __restrict__ ol) {
    const int t = blockIdx.x;
    const float4 v = ((const float4*)(x + t * kD))[threadIdx.x];
    float ss = v.x*v.x + v.y*v.y + v.z*v.z + v.w*v.w;
    ss = block_reduce_sum_256(ss);
    const float scale = rsqrtf(ss * (1.0f / kD) + kEPS);
    const float4 wv = ((const float4*)w)[threadIdx.x];
    const float a = v.x * scale * wv.x, b = v.y * scale * wv.y;
    const float c = v.z * scale * wv.z, d = v.w * scale * wv.w;
    __nv_bfloat162 l0, l1;
    const __nv_bfloat162 h0 = split_pair(a, b, l0);
    const __nv_bfloat162 h1 = split_pair(c, d, l1);
    ((__nv_bfloat162*)(oh + t * kD))[threadIdx.x * 2 + 0] = h0;
    ((__nv_bfloat162*)(oh + t * kD))[threadIdx.x * 2 + 1] = h1;
    ((__nv_bfloat162*)(ol + t * kD))[threadIdx.x * 2 + 0] = l0;
    ((__nv_bfloat162*)(ol + t * kD))[threadIdx.x * 2 + 1] = l1;
}

// ---------------- K1c: transpose + split convert: W[K][N] -> Bh/Bl [N][K] ----------------
__global__ void transpose_convert_kernel(const float* __restrict__ W,
                                         __nv_bfloat16* __restrict__ Bh,
                                         __nv_bfloat16* __restrict__ Bl,
                                         int K, int N) {
    __shared__ float tile[32][33];
    const int n0 = blockIdx.x * 32, k0 = blockIdx.y * 32;
    const int tx = threadIdx.x, ty = threadIdx.y;
    #pragma unroll
    for (int i = ty; i < 32; i += 8)
        tile[i][tx] = W[(size_t)(k0 + i) * N + n0 + tx];
    __syncthreads();
    #pragma unroll
    for (int i = ty; i < 32; i += 8) {
        const float v = tile[tx][i];          // k_local=tx, n_local=i
        const __nv_bfloat16 h = __float2bfloat16(v);
        Bh[(size_t)(n0 + i) * K + k0 + tx] = h;
        Bl[(size_t)(n0 + i) * K + k0 + tx] = __float2bfloat16(v - __bfloat162float(h));
    }
}

// ---------------- K2: residual add + rmsnorm ----------------
__global__ void resid_rmsnorm_kernel(const float* __restrict__ a,
                                     const float* __restrict__ b,
                                     const float* __restrict__ w,
                                     float* __restrict__ resid,
                                     float* __restrict__ xf) {
    const int t = blockIdx.x;
    const float4 va = ((const float4*)(a + t * kD))[threadIdx.x];
    const float4 vb = ((const float4*)(b + t * kD))[threadIdx.x];
    float4 v;
    v.x = va.x + vb.x; v.y = va.y + vb.y; v.z = va.z + vb.z; v.w = va.w + vb.w;
    ((float4*)(resid + t * kD))[threadIdx.x] = v;
    float ss = v.x*v.x + v.y*v.y + v.z*v.z + v.w*v.w;
    ss = block_reduce_sum_256(ss);
    const float scale = rsqrtf(ss * (1.0f / kD) + kEPS);
    const float4 wv = ((const float4*)w)[threadIdx.x];
    float4 o;
    o.x = v.x * scale * wv.x; o.y = v.y * scale * wv.y;
    o.z = v.z * scale * wv.z; o.w = v.w * scale * wv.w;
    ((float4*)(xf + t * kD))[threadIdx.x] = o;
}

// ---------------- K3: HMMA bf16 split GEMM, 3-stage cp.async, 1 barrier/chunk ----
constexpr int kTileBytes  = 128 * 64;          // one operand tile, 8KB
constexpr int kStageBytes = 4 * kTileBytes;    // Ah|Al|Bh|Bl, 32KB
constexpr int kGemmStages = 3;
constexpr int kGemmSmemDyn = kGemmStages * kStageBytes;  // 96KB

__global__ __launch_bounds__(256) void gemm_mma_kernel(const __nv_bfloat16* __restrict__ Ah,
                                                       const __nv_bfloat16* __restrict__ Al,
                                                       const __nv_bfloat16* __restrict__ Bh,
                                                       const __nv_bfloat16* __restrict__ Bl,
                                                       float* __restrict__ C,
                                                       int K, int N) {
    extern __shared__ __align__(128) char dynsm[];
    const uint32_t sbase = smem_u32(dynsm);
    const int tid  = threadIdx.x;
    const int wid  = tid >> 5;
    const int lane = tid & 31;
    const int wm = wid >> 2;           // 0..1 : warp row block of 64
    const int wn = wid & 3;            // 0..3 : warp col block of 32
    const int m0 = blockIdx.y * 128;
    const int n0 = blockIdx.x * 128;

    float acc[4][4][4];
    #pragma unroll
    for (int i = 0; i < 4; i++)
        #pragma unroll
        for (int j = 0; j < 4; j++)
            #pragma unroll
            for (int r = 0; r < 4; r++) acc[i][j][r] = 0.f;

    const int lr = lane & 7;
    const int lm = lane >> 3;
    const int a_row_off = ((lm & 1) << 3) + lr;
    const int a_kh      = lm >> 1;
    const int b_row_off = ((lm >> 1) << 3) + lr;
    const int b_kh      = lm & 1;

    auto load_stage = [&](int stage, int c) {
        const uint32_t sb = sbase + stage * kStageBytes;
        #pragma unroll
        for (int i = 0; i < 2; i++) {
            const int idx  = i * 256 + tid;      // 0..511
            const int row  = idx >> 2;
            const int unit = idx & 3;
            const uint32_t so = sw64(row * 64 + unit * 16);
            const size_t ga = (size_t)(m0 + row) * K + c * 32 + unit * 8;
            const size_t gb = (size_t)(n0 + row) * K + c * 32 + unit * 8;
            cp_async16(sb + 0 * kTileBytes + so, Ah + ga);
            cp_async16(sb + 1 * kTileBytes + so, Al + ga);
            cp_async16(sb + 2 * kTileBytes + so, Bh + gb);
            cp_async16(sb + 3 * kTileBytes + so, Bl + gb);
        }
        cp_commit();
    };

    const int nchunks = K >> 5;        // K/32
    load_stage(0, 0);
    load_stage(1, 1);
    for (int c = 0; c < nchunks; c++) {
        // wait for chunk c's group (allow <=1 newer pending)
        if (c + 1 < nchunks)
            asm volatile("cp.async.wait_group 1;" ::: "memory");
        else
            asm volatile("cp.async.wait_group 0;" ::: "memory");
        __syncthreads();   // also: all warps done computing chunk c-1
        // issue load of chunk c+2 into slot (c+2)%3 == (c-1)%3 (safe post-barrier)
        if (c + 2 < nchunks) load_stage((c + 2) % kGemmStages, c + 2);

        const uint32_t bAh = sbase + (c % kGemmStages) * kStageBytes;
        const uint32_t bAl = bAh + kTileBytes;
        const uint32_t bBh = bAh + 2 * kTileBytes;
        const uint32_t bBl = bAh + 3 * kTileBytes;
        #pragma unroll
        for (int ks = 0; ks < 2; ks++) {
            uint32_t fah[4][4], fal[4][4], fbh[4][2], fbl[4][2];
            const int aunit = ks * 2 + a_kh;
            #pragma unroll
            for (int mt = 0; mt < 4; mt++) {
                const int row = wm * 64 + mt * 16 + a_row_off;
                const uint32_t so = sw64(row * 64 + aunit * 16);
                ldsm4(fah[mt], bAh + so);
                ldsm4(fal[mt], bAl + so);
            }
            const int bunit = ks * 2 + b_kh;
            #pragma unroll
            for (int np = 0; np < 2; np++) {
                const int row = wn * 32 + np * 16 + b_row_off;
                const uint32_t so = sw64(row * 64 + bunit * 16);
                uint32_t t4[4];
                ldsm4(t4, bBh + so);
                fbh[np * 2][0] = t4[0]; fbh[np * 2][1] = t4[1];
                fbh[np * 2 + 1][0] = t4[2]; fbh[np * 2 + 1][1] = t4[3];
                ldsm4(t4, bBl + so);
                fbl[np * 2][0] = t4[0]; fbl[np * 2][1] = t4[1];
                fbl[np * 2 + 1][0] = t4[2]; fbl[np * 2 + 1][1] = t4[3];
            }
            #pragma unroll
            for (int mt = 0; mt < 4; mt++) {
                #pragma unroll
                for (int nt = 0; nt < 4; nt++) {
                    hmma(acc[mt][nt], fah[mt], fbh[nt]);
                    hmma(acc[mt][nt], fah[mt], fbl[nt]);
                    hmma(acc[mt][nt], fal[mt], fbh[nt]);
                }
            }
        }
    }
    const int gid = lane >> 2;
    const int tig = lane & 3;
    #pragma unroll
    for (int mt = 0; mt < 4; mt++) {
        #pragma unroll
        for (int nt = 0; nt < 4; nt++) {
            const int row = m0 + wm * 64 + mt * 16 + gid;
            const int col = n0 + wn * 32 + nt * 8 + tig * 2;
            *(float2*)(C + (size_t)row * N + col) =
                make_float2(acc[mt][nt][0], acc[mt][nt][1]);
            *(float2*)(C + (size_t)(row + 8) * N + col) =
                make_float2(acc[mt][nt][2], acc[mt][nt][3]);
        }
    }
}

// ---------------- K4: l2norm + rope -> bf16 q/k; split v -> bf16 hi/lo ----------------
__global__ void qkprep_kernel(const float* __restrict__ qkv,
                              __nv_bfloat16* __restrict__ qh,
                              __nv_bfloat16* __restrict__ kh,
                              __nv_bfloat16* __restrict__ vh,
                              __nv_bfloat16* __restrict__ vl) {
    const int t = blockIdx.x;
    const int warp = threadIdx.x >> 5;
    const int lane = threadIdx.x & 31;
    const float inv_freq = powf(kTHETA, -(float)lane / 32.0f);
    const float freq = (float)t * inv_freq;
    const float c = cosf(freq), sn = sinf(freq);
    #pragma unroll
    for (int hh = 0; hh < 2; hh++) {
        const int h = warp * 2 + hh;
        const size_t hbase = ((size_t)h * kS + t) * kHD;
        #pragma unroll
        for (int qk = 0; qk < 2; qk++) {
            const float* src = qkv + t * (3 * kD) + qk * kD + h * kHD;
            float v1 = src[lane];
            float v2 = src[lane + 32];
            float ss = v1 * v1 + v2 * v2;
            #pragma unroll
            for (int o = 16; o; o >>= 1) ss += __shfl_xor_sync(0xffffffffu, ss, o);
            const float inv = 1.0f / fmaxf(sqrtf(ss), kEPS);
            v1 *= inv; v2 *= inv;
            const float o1 =  v1 * c + v2 * sn;
            const float o2 = -v1 * sn + v2 * c;
            __nv_bfloat16* dst = (qk ? kh : qh) + hbase;
            dst[lane]      = __float2bfloat16(o1);
            dst[lane + 32] = __float2bfloat16(o2);
        }
        // v split
        const float* vs = qkv + t * (3 * kD) + 2 * kD + h * kHD;
        #pragma unroll
        for (int p = 0; p < 2; p++) {
            const int d = lane + p * 32;
            const float v = vs[d];
            const __nv_bfloat16 hv = __float2bfloat16(v);
            vh[hbase + d] = hv;
            vl[hbase + d] = __float2bfloat16(v - __bfloat162float(hv));
        }
    }
}

// ---------------- K5: causal attention on HMMA, 2-stage cp.async K/V ----------------
// dyn smem: Q (8KB) | stage0: K,Vh,Vl (24KB) | stage1: K,Vh,Vl (24KB) = 56KB
constexpr int kAttnTile   = 64 * 128;          // 8KB
constexpr int kAttnStage  = 3 * kAttnTile;     // 24KB
constexpr int kAttnSmemDyn = kAttnTile + 2 * kAttnStage;  // 56KB

__global__ __launch_bounds__(128) void attn_kernel(const __nv_bfloat16* __restrict__ qg,
                                                   const __nv_bfloat16* __restrict__ kg,
                                                   const __nv_bfloat16* __restrict__ vhg,
                                                   const __nv_bfloat16* __restrict__ vlg,
                                                   __nv_bfloat16* __restrict__ ah,
                                                   __nv_bfloat16* __restrict__ al) {
    const int h  = blockIdx.x;
    const int qb = (gridDim.y - 1) - blockIdx.y;   // LPT
    const int tid = threadIdx.x;
    const int wid = tid >> 5;
    const int lane = tid & 31;
    extern __shared__ __align__(128) char asm_dyn[];
    const uint32_t bQ = smem_u32(asm_dyn);

    // Q tile (direct stores; needed immediately)
    #pragma unroll
    for (int i = 0; i < 4; i++) {
        const int idx = i * 128 + tid;       // 0..511
        const int row = idx >> 3, unit = idx & 7;
        *(uint4*)(asm_dyn + sw128(row * 128 + unit * 16)) =
            *(const uint4*)(qg + ((size_t)h * kS + qb * 64 + row) * kHD + unit * 8);
    }

    auto load_tile = [&](int stage, int kt) {
        const uint32_t sb = bQ + kAttnTile + stage * kAttnStage;
        #pragma unroll
        for (int i = 0; i < 4; i++) {
            const int idx = i * 128 + tid;
            const int row = idx >> 3, unit = idx & 7;
            const uint32_t sw = sw128(row * 128 + unit * 16);
            const size_t gi = ((size_t)h * kS + kt * 64 + row) * kHD + unit * 8;
            cp_async16(sb + 0 * kAttnTile + sw, kg + gi);
            cp_async16(sb + 1 * kAttnTile + sw, vhg + gi);
            cp_async16(sb + 2 * kAttnTile + sw, vlg + gi);
        }
        cp_commit();
    };

    load_tile(0, 0);
    __syncthreads();   // Q visible to all warps

    const int lr = lane & 7;
    const int lm = lane >> 3;
    const int a_row = wid * 16 + ((lm & 1) << 3) + lr;
    const int a_kh  = lm >> 1;
    const int b_row = ((lm >> 1) << 3) + lr;
    const int b_kh  = lm & 1;

    uint32_t qa[4][4];
    #pragma unroll
    for (int cc = 0; cc < 4; cc++)
        ldsm4(qa[cc], bQ + sw128(a_row * 128 + (cc * 2 + a_kh) * 16));

    float oacc[8][4];
    #pragma unroll
    for (int j = 0; j < 8; j++)
        #pragma unroll
        for (int r = 0; r < 4; r++) oacc[j][r] = 0.f;
    float l0 = 0.f, l1 = 0.f;

    const int gid = lane >> 2;
    const int tig = lane & 3;
    const int qloc0 = wid * 16 + gid;
    const int ntiles = qb + 1;

    for (int kt = 0; kt < ntiles; kt++) {
        asm volatile("cp.async.wait_group 0;" ::: "memory");
        __syncthreads();   // tile kt landed; all warps done with tile kt-1's buffers
        if (kt + 1 < ntiles) load_tile((kt + 1) & 1, kt + 1);
        const uint32_t bK  = bQ + kAttnTile + (kt & 1) * kAttnStage;
        const uint32_t bVh = bK + kAttnTile;
        const uint32_t bVl = bK + 2 * kAttnTile;

        float sacc[8][4];
        #pragma unroll
        for (int j = 0; j < 8; j++)
            #pragma unroll
            for (int r = 0; r < 4; r++) sacc[j][r] = 0.f;
        #pragma unroll
        for (int cc = 0; cc < 4; cc++) {
            #pragma unroll
            for (int np = 0; np < 4; np++) {
                uint32_t t4[4];
                ldsm4(t4, bK + sw128((np * 16 + b_row) * 128 + (cc * 2 + b_kh) * 16));
                uint32_t f0[2] = {t4[0], t4[1]};
                uint32_t f1[2] = {t4[2], t4[3]};
                hmma(sacc[np * 2],     qa[cc], f0);
                hmma(sacc[np * 2 + 1], qa[cc], f1);
            }
        }
        const bool diag = (kt == qb);
        #pragma unroll
        for (int j = 0; j < 8; j++) {
            float p0 = exp_small(sacc[j][0] * 0.125f);
            float p1 = exp_small(sacc[j][1] * 0.125f);
            float p2 = exp_small(sacc[j][2] * 0.125f);
            float p3 = exp_small(sacc[j][3] * 0.125f);
            if (diag) {
                const int k0 = j * 8 + tig * 2;
                if (k0 > qloc0)     p0 = 0.f;
                if (k0 + 1 > qloc0) p1 = 0.f;
                if (k0 > qloc0 + 8)     p2 = 0.f;
                if (k0 + 1 > qloc0 + 8) p3 = 0.f;
            }
            l0 += p0 + p1;
            l1 += p2 + p3;
            sacc[j][0] = p0; sacc[j][1] = p1; sacc[j][2] = p2; sacc[j][3] = p3;
        }
        uint32_t pah[4][4], pal[4][4];
        #pragma unroll
        for (int cc = 0; cc < 4; cc++) {
            #pragma unroll
            for (int half = 0; half < 2; half++) {
                const int j = 2 * cc + half;
                __nv_bfloat162 lo01, lo23;
                const __nv_bfloat162 h01 = split_pair(sacc[j][0], sacc[j][1], lo01);
                const __nv_bfloat162 h23 = split_pair(sacc[j][2], sacc[j][3], lo23);
                pah[cc][half * 2 + 0] = *(const uint32_t*)&h01;
                pah[cc][half * 2 + 1] = *(const uint32_t*)&h23;
                pal[cc][half * 2 + 0] = *(const uint32_t*)&lo01;
                pal[cc][half * 2 + 1] = *(const uint32_t*)&lo23;
            }
        }
        #pragma unroll
        for (int cc = 0; cc < 4; cc++) {
            const int vrow = cc * 16 + ((lm & 1) << 3) + lr;
            #pragma unroll
            for (int jp = 0; jp < 4; jp++) {
                const int dunit = jp * 2 + (lm >> 1);
                uint32_t t4[4];
                ldsm4t(t4, bVh + sw128(vrow * 128 + dunit * 16));
                uint32_t f0[2] = {t4[0], t4[1]};
                uint32_t f1[2] = {t4[2], t4[3]};
                hmma(oacc[jp * 2],     pah[cc], f0);
                hmma(oacc[jp * 2 + 1], pah[cc], f1);
                hmma(oacc[jp * 2],     pal[cc], f0);
                hmma(oacc[jp * 2 + 1], pal[cc], f1);
                ldsm4t(t4, bVl + sw128(vrow * 128 + dunit * 16));
                uint32_t g0[2] = {t4[0], t4[1]};
                uint32_t g1[2] = {t4[2], t4[3]};
                hmma(oacc[jp * 2],     pah[cc], g0);
                hmma(oacc[jp * 2 + 1], pah[cc], g1);
            }
        }
    }
    l0 += __shfl_xor_sync(0xffffffffu, l0, 1);
    l0 += __shfl_xor_sync(0xffffffffu, l0, 2);
    l1 += __shfl_xor_sync(0xffffffffu, l1, 1);
    l1 += __shfl_xor_sync(0xffffffffu, l1, 2);
    const float inv0 = 1.0f / l0;
    const float inv1 = 1.0f / l1;
    const int q0 = qb * 64 + wid * 16 + gid;
    #pragma unroll
    for (int jd = 0; jd < 8; jd++) {
        const int d = h * kHD + jd * 8 + tig * 2;
        __nv_bfloat162 lo;
        __nv_bfloat162 hi = split_pair(oacc[jd][0] * inv0, oacc[jd][1] * inv0, lo);
        *(__nv_bfloat162*)(ah + (size_t)q0 * kD + d) = hi;
        *(__nv_bfloat162*)(al + (size_t)q0 * kD + d) = lo;
        hi = split_pair(oacc[jd][2] * inv1, oacc[jd][3] * inv1, lo);
        *(__nv_bfloat162*)(ah + (size_t)(q0 + 8) * kD + d) = hi;
        *(__nv_bfloat162*)(al + (size_t)(q0 + 8) * kD + d) = lo;
    }
}

// ---------------- K6: gathered routing GEMM ----------------
__global__ __launch_bounds__(256) void route_gemm_kernel(const float* __restrict__ xf,
                                                         const float* __restrict__ keys,
                                                         const int* __restrict__ indices,
                                                         float* __restrict__ G) {
    const int j = blockIdx.x;
    const int c = blockIdx.y;
    const int e = indices[c * kET + j];
    __shared__ float4 kcol[8 * 256];  // [h2][d4] : 8 heads x 1024 floats
    #pragma unroll
    for (int r = 0; r < 8; r++) {
        const int idx = r * 256 + threadIdx.x;
        const int h2 = idx >> 8;
        const int d4 = idx & 255;
        const float* base = keys + (size_t)h2 * kD * kE + (size_t)(d4 * 4) * kE + e;
        float4 v;
        v.x = __ldg(base);
        v.y = __ldg(base + kE);
        v.z = __ldg(base + 2 * kE);
        v.w = __ldg(base + 3 * kE);
        kcol[idx] = v;
    }
    __syncthreads();
    const int warp = threadIdx.x >> 5;
    const int lane = threadIdx.x & 31;
    for (int tt = 0; tt < 16; tt++) {
        const int t = c * kN + warp * 16 + tt;
        float acc[8];
        #pragma unroll
        for (int i = 0; i < 8; i++) acc[i] = 0.f;
        const float4* xp = (const float4*)(xf + t * kD);
        #pragma unroll
        for (int i = 0; i < 8; i++) {
            const float4 xv = xp[i * 32 + lane];
            #pragma unroll
            for (int h2 = 0; h2 < 8; h2++) {
                const float4 kv = kcol[h2 * 256 + i * 32 + lane];
                acc[h2] += xv.x * kv.x + xv.y * kv.y + xv.z * kv.z + xv.w * kv.w;
            }
        }
        #pragma unroll
        for (int h2 = 0; h2 < 8; h2++) {
            float s = acc[h2];
            #pragma unroll
            for (int o = 16; o; o >>= 1) s += __shfl_xor_sync(0xffffffffu, s, o);
            if (lane == 0) G[((size_t)t * kET + j) * 8 + h2] = s;
        }
    }
}

// ---------------- K7: combine gate weights ----------------
__global__ void combine_kernel(const float* __restrict__ G,
                               const float* __restrict__ scores,
                               const int* __restrict__ indices,
                               const float* __restrict__ head_probs,
                               const float* __restrict__ score_probs,
                               float* __restrict__ wbuf) {
    const int tj = blockIdx.x * blockDim.x + threadIdx.x;  // T*ET
    if (tj >= kT * kET) return;
    const int t = tj >> 4, j = tj & 15;
    const int c = t >> 7;
    const int e = indices[c * kET + j];
    const int r = j >> 2;
    const float* sp0 = score_probs + ((size_t)r * kE + e) * kH;
    const float* sp1 = score_probs + (size_t)kRE * kE * kH + ((size_t)r * kE + e) * kH;
    const float* hp = head_probs + ((size_t)r * kE + e) * kH;
    const float* sc = scores + ((size_t)t * kET + j) * kH;
    const float* g = G + (size_t)tj * 8;
    float acc = 0.f;
    #pragma unroll
    for (int h = 0; h < kH; h++) {
        const float x = sp0[h] * g[h >> 1] + sp1[h] * sc[h];
        const float sig = 1.0f / (1.0f + __expf(-x));
        acc += sig * hp[h];
    }
    wbuf[tj] = acc;
}

// ---------------- K8: expert FFN + final residual ----------------
__global__ __launch_bounds__(256) void expert_kernel(const float* __restrict__ xf,
                                                     const float* __restrict__ experts,
                                                     const int* __restrict__ indices,
                                                     const float* __restrict__ wbuf,
                                                     const float* __restrict__ resid,
                                                     float* __restrict__ out) {
    const int t = blockIdx.x;
    const int c = t >> 7;
    __shared__ int es[kET];
    __shared__ float h01[2 * kET];
    __shared__ float act_s[kET];
    if (threadIdx.x < kET) es[threadIdx.x] = indices[c * kET + threadIdx.x];
    __syncthreads();
    const int warp = threadIdx.x >> 5;
    const int lane = threadIdx.x & 31;
    const float4* xp = (const float4*)(xf + t * kD);
    #pragma unroll
    for (int jj = 0; jj < 2; jj++) {
        const int j = warp * 2 + jj;
        const int e = es[j];
        const float4* w0 = (const float4*)(experts + ((size_t)0 * kE + e) * kD);
        const float4* w1 = (const float4*)(experts + ((size_t)1 * kE + e) * kD);
        float a0 = 0.f, a1 = 0.f;
        #pragma unroll
        for (int i = 0; i < 8; i++) {
            const float4 xv = xp[i * 32 + lane];
            const float4 v0 = w0[i * 32 + lane];
            const float4 v1 = w1[i * 32 + lane];
            a0 += xv.x * v0.x + xv.y * v0.y + xv.z * v0.z + xv.w * v0.w;
            a1 += xv.x * v1.x + xv.y * v1.y + xv.z * v1.z + xv.w * v1.w;
        }
        #pragma unroll
        for (int o = 16; o; o >>= 1) {
            a0 += __shfl_xor_sync(0xffffffffu, a0, o);
            a1 += __shfl_xor_sync(0xffffffffu, a1, o);
        }
        if (lane == 0) {
            h01[j] = a0;
            h01[kET + j] = a1;
        }
    }
    __syncthreads();
    if (threadIdx.x < kET) {
        const int j = threadIdx.x;
        const float h0 = h01[j], h1 = h01[kET + j];
        const float silu = h0 / (1.0f + __expf(-h0));
        act_s[j] = silu * h1 * wbuf[t * kET + j];
    }
    __syncthreads();
    float4 acc = ((const float4*)(resid + t * kD))[threadIdx.x];
    #pragma unroll
    for (int j = 0; j < kET; j++) {
        const float a = act_s[j];
        const float4 wv = ((const float4*)(experts + ((size_t)2 * kE + es[j]) * kD))[threadIdx.x];
        acc.x += a * wv.x; acc.y += a * wv.y; acc.z += a * wv.z; acc.w += a * wv.w;
    }
    ((float4*)(out + t * kD))[threadIdx.x] = acc;
}

// ---------------- launch ----------------
extern "C" void kernel_launch(void* const* d_in, const int* in_sizes, int n_in,
                              void* d_out, int out_size) {
    const float* x_input     = (const float*)d_in[0];
    const int*   indices     = (const int*)  d_in[1];
    const float* scores      = (const float*)d_in[2];
    const float* attn_w      = (const float*)d_in[3];
    const float* attn_out_w  = (const float*)d_in[4];
    const float* attn_norm_w = (const float*)d_in[5];
    const float* ffn_norm_w  = (const float*)d_in[6];
    const float* ffn_experts = (const float*)d_in[7];
    const float* keys        = (const float*)d_in[8];
    const float* head_probs  = (const float*)d_in[9];
    const float* score_probs = (const float*)d_in[10];
    float* out = (float*)d_out;

    float *qkv, *proj, *resid, *xf, *G, *wb;
    __nv_bfloat16 *xnh, *xnl, *w1h, *w1l, *w2h, *w2l, *ah, *al, *qh, *kh, *vh, *vl;
    cudaGetSymbolAddress((void**)&qkv,   g_qkv);
    cudaGetSymbolAddress((void**)&proj,  g_proj);
    cudaGetSymbolAddress((void**)&resid, g_resid);
    cudaGetSymbolAddress((void**)&xf,    g_xf);
    cudaGetSymbolAddress((void**)&G,     g_G);
    cudaGetSymbolAddress((void**)&wb,    g_w);
    cudaGetSymbolAddress((void**)&xnh,   g_xnh);
    cudaGetSymbolAddress((void**)&xnl,   g_xnl);
    cudaGetSymbolAddress((void**)&w1h,   g_w1h);
    cudaGetSymbolAddress((void**)&w1l,   g_w1l);
    cudaGetSymbolAddress((void**)&w2h,   g_w2h);
    cudaGetSymbolAddress((void**)&w2l,   g_w2l);
    cudaGetSymbolAddress((void**)&ah,    g_ah);
    cudaGetSymbolAddress((void**)&al,    g_al);
    cudaGetSymbolAddress((void**)&qh,    g_qh);
    cudaGetSymbolAddress((void**)&kh,    g_kh);
    cudaGetSymbolAddress((void**)&vh,    g_vh);
    cudaGetSymbolAddress((void**)&vl,    g_vl);

    cudaFuncSetAttribute(gemm_mma_kernel,
                         cudaFuncAttributeMaxDynamicSharedMemorySize, kGemmSmemDyn);
    cudaFuncSetAttribute(attn_kernel,
                         cudaFuncAttributeMaxDynamicSharedMemorySize, kAttnSmemDyn);

    // weight conversions (deterministic every call)
    transpose_convert_kernel<<<dim3(3 * kD / 32, kD / 32), dim3(32, 8)>>>(attn_w, w1h, w1l, kD, 3 * kD);
    transpose_convert_kernel<<<dim3(kD / 32, kD / 32), dim3(32, 8)>>>(attn_out_w, w2h, w2l, kD, kD);

    rmsnorm_bf16_kernel<<<kT, 256>>>(x_input, attn_norm_w, xnh, xnl);
    gemm_mma_kernel<<<dim3(3 * kD / 128, kT / 128), 256, kGemmSmemDyn>>>(xnh, xnl, w1h, w1l, qkv, kD, 3 * kD);
    qkprep_kernel<<<kT, 256>>>(qkv, qh, kh, vh, vl);
    attn_kernel<<<dim3(kNH, kS / 64), 128, kAttnSmemDyn>>>(qh, kh, vh, vl, ah, al);
    gemm_mma_kernel<<<dim3(kD / 128, kT / 128), 256, kGemmSmemDyn>>>(ah, al, w2h, w2l, proj, kD, kD);
    resid_rmsnorm_kernel<<<kT, 256>>>(proj, x_input, ffn_norm_w, resid, xf);
    route_gemm_kernel<<<dim3(kET, kBC), 256>>>(xf, keys, indices, G);
    combine_kernel<<<(kT * kET + 255) / 256, 256>>>(G, scores, indices, head_probs, score_probs, wb);
    expert_kernel<<<kT, 256>>>(xf, ffn_experts, indices, wb, resid, out);
}

// round 14
// speedup vs baseline: 1.0046x; 1.0046x over previous
#include <cuda_runtime.h>
#include <cuda_bf16.h>
#include <math.h>
#include <stdint.h>

// ---------------- problem constants ----------------
constexpr int kD   = 1024;
constexpr int kHD  = 64;
constexpr int kNH  = 16;
constexpr int kH   = 16;   // routing heads
constexpr int kKH  = 8;
constexpr int kN   = 128;  // tokens per block
constexpr int kE   = 4096;
constexpr int kRE  = 4;
constexpr int kDE  = 4;
constexpr int kET  = 16;   // RE*DE
constexpr int kS   = 2048;
constexpr int kT   = 2048;
constexpr int kBC  = 16;   // T / N
constexpr float kEPS   = 1e-5f;
constexpr float kTHETA = 10000.0f;

// ---------------- device scratch ----------------
__device__ float g_qkv  [kT * 3 * kD];    // qkv
__device__ float g_proj [kT * kD];        // attn out-proj
__device__ float g_resid[kT * kD];        // x_ffn_input
__device__ float g_xf   [kT * kD];        // rmsnorm(x_ffn_input)
__device__ float g_G    [kT * kET * 8];   // gathered routing dots per (t, j, h2)
__device__ float g_w    [kT * kET];       // combined gate weights
// split-bf16 buffers for tensor-core GEMMs / attention
__device__ __nv_bfloat16 g_xnh[kT * kD];          // rmsnorm(x) hi
__device__ __nv_bfloat16 g_xnl[kT * kD];          // rmsnorm(x) lo
__device__ __nv_bfloat16 g_w1h[3 * kD * kD];      // attn_w transposed [3D][D] hi
__device__ __nv_bfloat16 g_w1l[3 * kD * kD];
__device__ __nv_bfloat16 g_w2h[kD * kD];          // attn_out_w transposed hi
__device__ __nv_bfloat16 g_w2l[kD * kD];
__device__ __nv_bfloat16 g_ah [kT * kD];          // attention output hi
__device__ __nv_bfloat16 g_al [kT * kD];          // attention output lo
__device__ __nv_bfloat16 g_qh [kNH * kS * kHD];   // rope'd q bf16, (h,s,d)
__device__ __nv_bfloat16 g_kh [kNH * kS * kHD];   // rope'd k bf16
__device__ __nv_bfloat16 g_vh [kNH * kS * kHD];   // v hi, (h,s,d)
__device__ __nv_bfloat16 g_vl [kNH * kS * kHD];   // v lo

// ---------------- helpers ----------------
__device__ __forceinline__ float block_reduce_sum_256(float v) {
    __shared__ float red[8];
    #pragma unroll
    for (int o = 16; o; o >>= 1) v += __shfl_xor_sync(0xffffffffu, v, o);
    if ((threadIdx.x & 31) == 0) red[threadIdx.x >> 5] = v;
    __syncthreads();
    float s = 0.f;
    #pragma unroll
    for (int i = 0; i < 8; i++) s += red[i];
    __syncthreads();
    return s;
}

// exp(x) for |x| <= 0.13 : degree-4 Taylor, abs err ~3e-7, 4 FMA, no MUFU.
__device__ __forceinline__ float exp_small(float x) {
    float e = fmaf(x, 1.0f / 24.0f, 1.0f / 6.0f);
    e = fmaf(e, x, 0.5f);
    e = fmaf(e, x, 1.0f);
    e = fmaf(e, x, 1.0f);
    return e;
}

__device__ __forceinline__ __nv_bfloat162 split_pair(float a, float b,
                                                     __nv_bfloat162& lo) {
    __nv_bfloat16 ha = __float2bfloat16(a);
    __nv_bfloat16 hb = __float2bfloat16(b);
    lo = __nv_bfloat162(__float2bfloat16(a - __bfloat162float(ha)),
                        __float2bfloat16(b - __bfloat162float(hb)));
    return __nv_bfloat162(ha, hb);
}

__device__ __forceinline__ uint32_t smem_u32(const void* p) {
    uint32_t a;
    asm("{ .reg .u64 t; cvta.to.shared.u64 t, %1; cvt.u32.u64 %0, t; }" : "=r"(a) : "l"(p));
    return a;
}

__device__ __forceinline__ uint32_t sw128(uint32_t off) {
    return off ^ ((off >> 3) & 0x70);
}
__device__ __forceinline__ uint32_t sw64(uint32_t off) {
    return off ^ ((off >> 3) & 0x30);
}
__device__ __forceinline__ void ldsm4(uint32_t* d, uint32_t a) {
    asm volatile("ldmatrix.sync.aligned.m8n8.x4.shared.b16 {%0,%1,%2,%3}, [%4];"
        : "=r"(d[0]), "=r"(d[1]), "=r"(d[2]), "=r"(d[3]) : "r"(a));
}
__device__ __forceinline__ void ldsm4t(uint32_t* d, uint32_t a) {
    asm volatile("ldmatrix.sync.aligned.m8n8.x4.trans.shared.b16 {%0,%1,%2,%3}, [%4];"
        : "=r"(d[0]), "=r"(d[1]), "=r"(d[2]), "=r"(d[3]) : "r"(a));
}
__device__ __forceinline__ void hmma(float* d, const uint32_t* a, const uint32_t* b) {
    asm volatile("mma.sync.aligned.m16n8k16.row.col.f32.bf16.bf16.f32 "
        "{%0,%1,%2,%3}, {%4,%5,%6,%7}, {%8,%9}, {%0,%1,%2,%3};"
        : "+f"(d[0]), "+f"(d[1]), "+f"(d[2]), "+f"(d[3])
        : "r"(a[0]), "r"(a[1]), "r"(a[2]), "r"(a[3]), "r"(b[0]), "r"(b[1]));
}
__device__ __forceinline__ void cp_async16(uint32_t dst, const void* src) {
    asm volatile("cp.async.cg.shared.global [%0], [%1], 16;" :: "r"(dst), "l"(src) : "memory");
}
__device__ __forceinline__ void cp_commit() {
    asm volatile("cp.async.commit_group;" ::: "memory");
}

// ---------------- K1: rmsnorm -> split bf16 hi/lo ----------------
__global__ void rmsnorm_bf16_kernel(const float* __restrict__ x,
                                    const float* __restrict__ w,
                                    __nv_bfloat16* __restrict__ oh,
                                    __nv_bfloat16* __restrict__ ol) {
    const int t = blockIdx.x;
    const float4 v = ((const float4*)(x + t * kD))[threadIdx.x];
    float ss = v.x*v.x + v.y*v.y + v.z*v.z + v.w*v.w;
    ss = block_reduce_sum_256(ss);
    const float scale = rsqrtf(ss * (1.0f / kD) + kEPS);
    const float4 wv = ((const float4*)w)[threadIdx.x];
    const float a = v.x * scale * wv.x, b = v.y * scale * wv.y;
    const float c = v.z * scale * wv.z, d = v.w * scale * wv.w;
    __nv_bfloat162 l0, l1;
    const __nv_bfloat162 h0 = split_pair(a, b, l0);
    const __nv_bfloat162 h1 = split_pair(c, d, l1);
    ((__nv_bfloat162*)(oh + t * kD))[threadIdx.x * 2 + 0] = h0;
    ((__nv_bfloat162*)(oh + t * kD))[threadIdx.x * 2 + 1] = h1;
    ((__nv_bfloat162*)(ol + t * kD))[threadIdx.x * 2 + 0] = l0;
    ((__nv_bfloat162*)(ol + t * kD))[threadIdx.x * 2 + 1] = l1;
}

// ---------------- K1c: transpose + split convert: W[K][N] -> Bh/Bl [N][K] ----------------
__global__ void transpose_convert_kernel(const float* __restrict__ W,
                                         __nv_bfloat16* __restrict__ Bh,
                                         __nv_bfloat16* __restrict__ Bl,
                                         int K, int N) {
    __shared__ float tile[32][33];
    const int n0 = blockIdx.x * 32, k0 = blockIdx.y * 32;
    const int tx = threadIdx.x, ty = threadIdx.y;
    #pragma unroll
    for (int i = ty; i < 32; i += 8)
        tile[i][tx] = W[(size_t)(k0 + i) * N + n0 + tx];
    __syncthreads();
    #pragma unroll
    for (int i = ty; i < 32; i += 8) {
        const float v = tile[tx][i];          // k_local=tx, n_local=i
        const __nv_bfloat16 h = __float2bfloat16(v);
        Bh[(size_t)(n0 + i) * K + k0 + tx] = h;
        Bl[(size_t)(n0 + i) * K + k0 + tx] = __float2bfloat16(v - __bfloat162float(h));
    }
}

// ---------------- K2: residual add + rmsnorm ----------------
__global__ void resid_rmsnorm_kernel(const float* __restrict__ a,
                                     const float* __restrict__ b,
                                     const float* __restrict__ w,
                                     float* __restrict__ resid,
                                     float* __restrict__ xf) {
    const int t = blockIdx.x;
    const float4 va = ((const float4*)(a + t * kD))[threadIdx.x];
    const float4 vb = ((const float4*)(b + t * kD))[threadIdx.x];
    float4 v;
    v.x = va.x + vb.x; v.y = va.y + vb.y; v.z = va.z + vb.z; v.w = va.w + vb.w;
    ((float4*)(resid + t * kD))[threadIdx.x] = v;
    float ss = v.x*v.x + v.y*v.y + v.z*v.z + v.w*v.w;
    ss = block_reduce_sum_256(ss);
    const float scale = rsqrtf(ss * (1.0f / kD) + kEPS);
    const float4 wv = ((const float4*)w)[threadIdx.x];
    float4 o;
    o.x = v.x * scale * wv.x; o.y = v.y * scale * wv.y;
    o.z = v.z * scale * wv.z; o.w = v.w * scale * wv.w;
    ((float4*)(xf + t * kD))[threadIdx.x] = o;
}

// ---------------- K3: HMMA bf16 split GEMM, 3-stage cp.async, regs capped ----
constexpr int kTileBytes  = 128 * 64;          // one operand tile, 8KB
constexpr int kStageBytes = 4 * kTileBytes;    // Ah|Al|Bh|Bl, 32KB
constexpr int kGemmStages = 3;
constexpr int kGemmSmemDyn = kGemmStages * kStageBytes;  // 96KB

__global__ __launch_bounds__(256, 2) void gemm_mma_kernel(const __nv_bfloat16* __restrict__ Ah,
                                                          const __nv_bfloat16* __restrict__ Al,
                                                          const __nv_bfloat16* __restrict__ Bh,
                                                          const __nv_bfloat16* __restrict__ Bl,
                                                          float* __restrict__ C,
                                                          int K, int N) {
    extern __shared__ __align__(128) char dynsm[];
    const uint32_t sbase = smem_u32(dynsm);
    const int tid  = threadIdx.x;
    const int wid  = tid >> 5;
    const int lane = tid & 31;
    const int wm = wid >> 2;           // 0..1 : warp row block of 64
    const int wn = wid & 3;            // 0..3 : warp col block of 32
    const int m0 = blockIdx.y * 128;
    const int n0 = blockIdx.x * 128;

    float acc[4][4][4];
    #pragma unroll
    for (int i = 0; i < 4; i++)
        #pragma unroll
        for (int j = 0; j < 4; j++)
            #pragma unroll
            for (int r = 0; r < 4; r++) acc[i][j][r] = 0.f;

    const int lr = lane & 7;
    const int lm = lane >> 3;
    const int a_row_off = ((lm & 1) << 3) + lr;
    const int a_kh      = lm >> 1;
    const int b_row_off = ((lm >> 1) << 3) + lr;
    const int b_kh      = lm & 1;

    auto load_stage = [&](int stage, int c) {
        const uint32_t sb = sbase + stage * kStageBytes;
        #pragma unroll
        for (int i = 0; i < 2; i++) {
            const int idx  = i * 256 + tid;      // 0..511
            const int row  = idx >> 2;
            const int unit = idx & 3;
            const uint32_t so = sw64(row * 64 + unit * 16);
            const size_t ga = (size_t)(m0 + row) * K + c * 32 + unit * 8;
            const size_t gb = (size_t)(n0 + row) * K + c * 32 + unit * 8;
            cp_async16(sb + 0 * kTileBytes + so, Ah + ga);
            cp_async16(sb + 1 * kTileBytes + so, Al + ga);
            cp_async16(sb + 2 * kTileBytes + so, Bh + gb);
            cp_async16(sb + 3 * kTileBytes + so, Bl + gb);
        }
        cp_commit();
    };

    const int nchunks = K >> 5;        // K/32
    load_stage(0, 0);
    load_stage(1, 1);
    for (int c = 0; c < nchunks; c++) {
        if (c + 1 < nchunks)
            asm volatile("cp.async.wait_group 1;" ::: "memory");
        else
            asm volatile("cp.async.wait_group 0;" ::: "memory");
        __syncthreads();   // chunk c landed; all warps done computing chunk c-1
        if (c + 2 < nchunks) load_stage((c + 2) % kGemmStages, c + 2);

        const uint32_t bAh = sbase + (c % kGemmStages) * kStageBytes;
        const uint32_t bAl = bAh + kTileBytes;
        const uint32_t bBh = bAh + 2 * kTileBytes;
        const uint32_t bBl = bAh + 3 * kTileBytes;
        #pragma unroll
        for (int ks = 0; ks < 2; ks++) {
            uint32_t fah[4][4], fal[4][4], fbh[4][2], fbl[4][2];
            const int aunit = ks * 2 + a_kh;
            #pragma unroll
            for (int mt = 0; mt < 4; mt++) {
                const int row = wm * 64 + mt * 16 + a_row_off;
                const uint32_t so = sw64(row * 64 + aunit * 16);
                ldsm4(fah[mt], bAh + so);
                ldsm4(fal[mt], bAl + so);
            }
            const int bunit = ks * 2 + b_kh;
            #pragma unroll
            for (int np = 0; np < 2; np++) {
                const int row = wn * 32 + np * 16 + b_row_off;
                const uint32_t so = sw64(row * 64 + bunit * 16);
                uint32_t t4[4];
                ldsm4(t4, bBh + so);
                fbh[np * 2][0] = t4[0]; fbh[np * 2][1] = t4[1];
                fbh[np * 2 + 1][0] = t4[2]; fbh[np * 2 + 1][1] = t4[3];
                ldsm4(t4, bBl + so);
                fbl[np * 2][0] = t4[0]; fbl[np * 2][1] = t4[1];
                fbl[np * 2 + 1][0] = t4[2]; fbl[np * 2 + 1][1] = t4[3];
            }
            #pragma unroll
            for (int mt = 0; mt < 4; mt++) {
                #pragma unroll
                for (int nt = 0; nt < 4; nt++) {
                    hmma(acc[mt][nt], fah[mt], fbh[nt]);
                    hmma(acc[mt][nt], fah[mt], fbl[nt]);
                    hmma(acc[mt][nt], fal[mt], fbh[nt]);
                }
            }
        }
    }
    const int gid = lane >> 2;
    const int tig = lane & 3;
    #pragma unroll
    for (int mt = 0; mt < 4; mt++) {
        #pragma unroll
        for (int nt = 0; nt < 4; nt++) {
            const int row = m0 + wm * 64 + mt * 16 + gid;
            const int col = n0 + wn * 32 + nt * 8 + tig * 2;
            *(float2*)(C + (size_t)row * N + col) =
                make_float2(acc[mt][nt][0], acc[mt][nt][1]);
            *(float2*)(C + (size_t)(row + 8) * N + col) =
                make_float2(acc[mt][nt][2], acc[mt][nt][3]);
        }
    }
}

// ---------------- K4: l2norm + rope -> bf16 q/k; split v -> bf16 hi/lo ----------------
__global__ void qkprep_kernel(const float* __restrict__ qkv,
                              __nv_bfloat16* __restrict__ qh,
                              __nv_bfloat16* __restrict__ kh,
                              __nv_bfloat16* __restrict__ vh,
                              __nv_bfloat16* __restrict__ vl) {
    const int t = blockIdx.x;
    const int warp = threadIdx.x >> 5;
    const int lane = threadIdx.x & 31;
    const float inv_freq = powf(kTHETA, -(float)lane / 32.0f);
    const float freq = (float)t * inv_freq;
    const float c = cosf(freq), sn = sinf(freq);
    #pragma unroll
    for (int hh = 0; hh < 2; hh++) {
        const int h = warp * 2 + hh;
        const size_t hbase = ((size_t)h * kS + t) * kHD;
        #pragma unroll
        for (int qk = 0; qk < 2; qk++) {
            const float* src = qkv + t * (3 * kD) + qk * kD + h * kHD;
            float v1 = src[lane];
            float v2 = src[lane + 32];
            float ss = v1 * v1 + v2 * v2;
            #pragma unroll
            for (int o = 16; o; o >>= 1) ss += __shfl_xor_sync(0xffffffffu, ss, o);
            const float inv = 1.0f / fmaxf(sqrtf(ss), kEPS);
            v1 *= inv; v2 *= inv;
            const float o1 =  v1 * c + v2 * sn;
            const float o2 = -v1 * sn + v2 * c;
            __nv_bfloat16* dst = (qk ? kh : qh) + hbase;
            dst[lane]      = __float2bfloat16(o1);
            dst[lane + 32] = __float2bfloat16(o2);
        }
        // v split
        const float* vs = qkv + t * (3 * kD) + 2 * kD + h * kHD;
        #pragma unroll
        for (int p = 0; p < 2; p++) {
            const int d = lane + p * 32;
            const float v = vs[d];
            const __nv_bfloat16 hv = __float2bfloat16(v);
            vh[hbase + d] = hv;
            vl[hbase + d] = __float2bfloat16(v - __bfloat162float(hv));
        }
    }
}

// ---------------- K5: causal attention on HMMA, 2-stage cp.async K/V ----------------
constexpr int kAttnTile   = 64 * 128;          // 8KB
constexpr int kAttnStage  = 3 * kAttnTile;     // 24KB
constexpr int kAttnSmemDyn = kAttnTile + 2 * kAttnStage;  // 56KB

__global__ __launch_bounds__(128) void attn_kernel(const __nv_bfloat16* __restrict__ qg,
                                                   const __nv_bfloat16* __restrict__ kg,
                                                   const __nv_bfloat16* __restrict__ vhg,
                                                   const __nv_bfloat16* __restrict__ vlg,
                                                   __nv_bfloat16* __restrict__ ah,
                                                   __nv_bfloat16* __restrict__ al) {
    const int h  = blockIdx.x;
    const int qb = (gridDim.y - 1) - blockIdx.y;   // LPT
    const int tid = threadIdx.x;
    const int wid = tid >> 5;
    const int lane = tid & 31;
    extern __shared__ __align__(128) char asm_dyn[];
    const uint32_t bQ = smem_u32(asm_dyn);

    #pragma unroll
    for (int i = 0; i < 4; i++) {
        const int idx = i * 128 + tid;       // 0..511
        const int row = idx >> 3, unit = idx & 7;
        *(uint4*)(asm_dyn + sw128(row * 128 + unit * 16)) =
            *(const uint4*)(qg + ((size_t)h * kS + qb * 64 + row) * kHD + unit * 8);
    }

    auto load_tile = [&](int stage, int kt) {
        const uint32_t sb = bQ + kAttnTile + stage * kAttnStage;
        #pragma unroll
        for (int i = 0; i < 4; i++) {
            const int idx = i * 128 + tid;
            const int row = idx >> 3, unit = idx & 7;
            const uint32_t sw = sw128(row * 128 + unit * 16);
            const size_t gi = ((size_t)h * kS + kt * 64 + row) * kHD + unit * 8;
            cp_async16(sb + 0 * kAttnTile + sw, kg + gi);
            cp_async16(sb + 1 * kAttnTile + sw, vhg + gi);
            cp_async16(sb + 2 * kAttnTile + sw, vlg + gi);
        }
        cp_commit();
    };

    load_tile(0, 0);
    __syncthreads();   // Q visible to all warps

    const int lr = lane & 7;
    const int lm = lane >> 3;
    const int a_row = wid * 16 + ((lm & 1) << 3) + lr;
    const int a_kh  = lm >> 1;
    const int b_row = ((lm >> 1) << 3) + lr;
    const int b_kh  = lm & 1;

    uint32_t qa[4][4];
    #pragma unroll
    for (int cc = 0; cc < 4; cc++)
        ldsm4(qa[cc], bQ + sw128(a_row * 128 + (cc * 2 + a_kh) * 16));

    float oacc[8][4];
    #pragma unroll
    for (int j = 0; j < 8; j++)
        #pragma unroll
        for (int r = 0; r < 4; r++) oacc[j][r] = 0.f;
    float l0 = 0.f, l1 = 0.f;

    const int gid = lane >> 2;
    const int tig = lane & 3;
    const int qloc0 = wid * 16 + gid;
    const int ntiles = qb + 1;

    for (int kt = 0; kt < ntiles; kt++) {
        asm volatile("cp.async.wait_group 0;" ::: "memory");
        __syncthreads();   // tile kt landed; all warps done with tile kt-1's buffers
        if (kt + 1 < ntiles) load_tile((kt + 1) & 1, kt + 1);
        const uint32_t bK  = bQ + kAttnTile + (kt & 1) * kAttnStage;
        const uint32_t bVh = bK + kAttnTile;
        const uint32_t bVl = bK + 2 * kAttnTile;

        float sacc[8][4];
        #pragma unroll
        for (int j = 0; j < 8; j++)
            #pragma unroll
            for (int r = 0; r < 4; r++) sacc[j][r] = 0.f;
        #pragma unroll
        for (int cc = 0; cc < 4; cc++) {
            #pragma unroll
            for (int np = 0; np < 4; np++) {
                uint32_t t4[4];
                ldsm4(t4, bK + sw128((np * 16 + b_row) * 128 + (cc * 2 + b_kh) * 16));
                uint32_t f0[2] = {t4[0], t4[1]};
                uint32_t f1[2] = {t4[2], t4[3]};
                hmma(sacc[np * 2],     qa[cc], f0);
                hmma(sacc[np * 2 + 1], qa[cc], f1);
            }
        }
        const bool diag = (kt == qb);
        #pragma unroll
        for (int j = 0; j < 8; j++) {
            float p0 = exp_small(sacc[j][0] * 0.125f);
            float p1 = exp_small(sacc[j][1] * 0.125f);
            float p2 = exp_small(sacc[j][2] * 0.125f);
            float p3 = exp_small(sacc[j][3] * 0.125f);
            if (diag) {
                const int k0 = j * 8 + tig * 2;
                if (k0 > qloc0)     p0 = 0.f;
                if (k0 + 1 > qloc0) p1 = 0.f;
                if (k0 > qloc0 + 8)     p2 = 0.f;
                if (k0 + 1 > qloc0 + 8) p3 = 0.f;
            }
            l0 += p0 + p1;
            l1 += p2 + p3;
            sacc[j][0] = p0; sacc[j][1] = p1; sacc[j][2] = p2; sacc[j][3] = p3;
        }
        uint32_t pah[4][4], pal[4][4];
        #pragma unroll
        for (int cc = 0; cc < 4; cc++) {
            #pragma unroll
            for (int half = 0; half < 2; half++) {
                const int j = 2 * cc + half;
                __nv_bfloat162 lo01, lo23;
                const __nv_bfloat162 h01 = split_pair(sacc[j][0], sacc[j][1], lo01);
                const __nv_bfloat162 h23 = split_pair(sacc[j][2], sacc[j][3], lo23);
                pah[cc][half * 2 + 0] = *(const uint32_t*)&h01;
                pah[cc][half * 2 + 1] = *(const uint32_t*)&h23;
                pal[cc][half * 2 + 0] = *(const uint32_t*)&lo01;
                pal[cc][half * 2 + 1] = *(const uint32_t*)&lo23;
            }
        }
        #pragma unroll
        for (int cc = 0; cc < 4; cc++) {
            const int vrow = cc * 16 + ((lm & 1) << 3) + lr;
            #pragma unroll
            for (int jp = 0; jp < 4; jp++) {
                const int dunit = jp * 2 + (lm >> 1);
                uint32_t t4[4];
                ldsm4t(t4, bVh + sw128(vrow * 128 + dunit * 16));
                uint32_t f0[2] = {t4[0], t4[1]};
                uint32_t f1[2] = {t4[2], t4[3]};
                hmma(oacc[jp * 2],     pah[cc], f0);
                hmma(oacc[jp * 2 + 1], pah[cc], f1);
                hmma(oacc[jp * 2],     pal[cc], f0);
                hmma(oacc[jp * 2 + 1], pal[cc], f1);
                ldsm4t(t4, bVl + sw128(vrow * 128 + dunit * 16));
                uint32_t g0[2] = {t4[0], t4[1]};
                uint32_t g1[2] = {t4[2], t4[3]};
                hmma(oacc[jp * 2],     pah[cc], g0);
                hmma(oacc[jp * 2 + 1], pah[cc], g1);
            }
        }
    }
    l0 += __shfl_xor_sync(0xffffffffu, l0, 1);
    l0 += __shfl_xor_sync(0xffffffffu, l0, 2);
    l1 += __shfl_xor_sync(0xffffffffu, l1, 1);
    l1 += __shfl_xor_sync(0xffffffffu, l1, 2);
    const float inv0 = 1.0f / l0;
    const float inv1 = 1.0f / l1;
    const int q0 = qb * 64 + wid * 16 + gid;
    #pragma unroll
    for (int jd = 0; jd < 8; jd++) {
        const int d = h * kHD + jd * 8 + tig * 2;
        __nv_bfloat162 lo;
        __nv_bfloat162 hi = split_pair(oacc[jd][0] * inv0, oacc[jd][1] * inv0, lo);
        *(__nv_bfloat162*)(ah + (size_t)q0 * kD + d) = hi;
        *(__nv_bfloat162*)(al + (size_t)q0 * kD + d) = lo;
        hi = split_pair(oacc[jd][2] * inv1, oacc[jd][3] * inv1, lo);
        *(__nv_bfloat162*)(ah + (size_t)(q0 + 8) * kD + d) = hi;
        *(__nv_bfloat162*)(al + (size_t)(q0 + 8) * kD + d) = lo;
    }
}

// ---------------- K6: gathered routing GEMM ----------------
__global__ __launch_bounds__(256) void route_gemm_kernel(const float* __restrict__ xf,
                                                         const float* __restrict__ keys,
                                                         const int* __restrict__ indices,
                                                         float* __restrict__ G) {
    const int j = blockIdx.x;
    const int c = blockIdx.y;
    const int e = indices[c * kET + j];
    __shared__ float4 kcol[8 * 256];  // [h2][d4] : 8 heads x 1024 floats
    #pragma unroll
    for (int r = 0; r < 8; r++) {
        const int idx = r * 256 + threadIdx.x;
        const int h2 = idx >> 8;
        const int d4 = idx & 255;
        const float* base = keys + (size_t)h2 * kD * kE + (size_t)(d4 * 4) * kE + e;
        float4 v;
        v.x = __ldg(base);
        v.y = __ldg(base + kE);
        v.z = __ldg(base + 2 * kE);
        v.w = __ldg(base + 3 * kE);
        kcol[idx] = v;
    }
    __syncthreads();
    const int warp = threadIdx.x >> 5;
    const int lane = threadIdx.x & 31;
    for (int tt = 0; tt < 16; tt++) {
        const int t = c * kN + warp * 16 + tt;
        float acc[8];
        #pragma unroll
        for (int i = 0; i < 8; i++) acc[i] = 0.f;
        const float4* xp = (const float4*)(xf + t * kD);
        #pragma unroll
        for (int i = 0; i < 8; i++) {
            const float4 xv = xp[i * 32 + lane];
            #pragma unroll
            for (int h2 = 0; h2 < 8; h2++) {
                const float4 kv = kcol[h2 * 256 + i * 32 + lane];
                acc[h2] += xv.x * kv.x + xv.y * kv.y + xv.z * kv.z + xv.w * kv.w;
            }
        }
        #pragma unroll
        for (int h2 = 0; h2 < 8; h2++) {
            float s = acc[h2];
            #pragma unroll
            for (int o = 16; o; o >>= 1) s += __shfl_xor_sync(0xffffffffu, s, o);
            if (lane == 0) G[((size_t)t * kET + j) * 8 + h2] = s;
        }
    }
}

// ---------------- K7: combine gate weights ----------------
__global__ void combine_kernel(const float* __restrict__ G,
                               const float* __restrict__ scores,
                               const int* __restrict__ indices,
                               const float* __restrict__ head_probs,
                               const float* __restrict__ score_probs,
                               float* __restrict__ wbuf) {
    const int tj = blockIdx.x * blockDim.x + threadIdx.x;  // T*ET
    if (tj >= kT * kET) return;
    const int t = tj >> 4, j = tj & 15;
    const int c = t >> 7;
    const int e = indices[c * kET + j];
    const int r = j >> 2;
    const float* sp0 = score_probs + ((size_t)r * kE + e) * kH;
    const float* sp1 = score_probs + (size_t)kRE * kE * kH + ((size_t)r * kE + e) * kH;
    const float* hp = head_probs + ((size_t)r * kE + e) * kH;
    const float* sc = scores + ((size_t)t * kET + j) * kH;
    const float* g = G + (size_t)tj * 8;
    float acc = 0.f;
    #pragma unroll
    for (int h = 0; h < kH; h++) {
        const float x = sp0[h] * g[h >> 1] + sp1[h] * sc[h];
        const float sig = 1.0f / (1.0f + __expf(-x));
        acc += sig * hp[h];
    }
    wbuf[tj] = acc;
}

// ---------------- K8: expert FFN + final residual (smem-cached experts) ----------
// grid (kBC, 8): block c-chunk, 16-token slice. Expert weights streamed through
// smem once per block instead of once per token (L2 traffic ~8x lower).
__global__ __launch_bounds__(256) void expert_kernel(const float* __restrict__ xf,
                                                     const float* __restrict__ experts,
                                                     const int* __restrict__ indices,
                                                     const float* __restrict__ wbuf,
                                                     const float* __restrict__ resid,
                                                     float* __restrict__ out) {
    const int c  = blockIdx.x;
    const int sl = blockIdx.y;            // 0..7
    const int t0 = c * kN + sl * 16;
    __shared__ int es[kET];
    __shared__ float act_s[16][17];
    __shared__ float xfs[16][132];
    __shared__ float w0s[16][132];
    __shared__ float w1s[16][132];
    const int tid = threadIdx.x;
    if (tid < kET) es[tid] = indices[c * kET + tid];
    __syncthreads();
    const int tt = tid >> 4;              // token 0..15
    const int ee = tid & 15;              // expert 0..15
    float a0 = 0.f, a1 = 0.f;
    for (int ch = 0; ch < 8; ch++) {
        #pragma unroll
        for (int i = 0; i < 2; i++) {
            const int fid = i * 256 + tid;        // 0..511
            const int row = fid >> 5, col = fid & 31;
            *(float4*)&xfs[row][col * 4] =
                *(const float4*)(xf + (size_t)(t0 + row) * kD + ch * 128 + col * 4);
            *(float4*)&w0s[row][col * 4] =
                *(const float4*)(experts + ((size_t)0 * kE + es[row]) * kD + ch * 128 + col * 4);
            *(float4*)&w1s[row][col * 4] =
                *(const float4*)(experts + ((size_t)1 * kE + es[row]) * kD + ch * 128 + col * 4);
        }
        __syncthreads();
        #pragma unroll 8
        for (int d4 = 0; d4 < 32; d4++) {
            const float4 xv = *(const float4*)&xfs[tt][d4 * 4];
            const float4 v0 = *(const float4*)&w0s[ee][d4 * 4];
            const float4 v1 = *(const float4*)&w1s[ee][d4 * 4];
            a0 += xv.x * v0.x + xv.y * v0.y + xv.z * v0.z + xv.w * v0.w;
            a1 += xv.x * v1.x + xv.y * v1.y + xv.z * v1.z + xv.w * v1.w;
        }
        __syncthreads();
    }
    {
        const float silu = a0 / (1.0f + __expf(-a0));
        act_s[tt][ee] = silu * a1 * wbuf[(size_t)(t0 + tt) * kET + ee];
    }
    __syncthreads();
    // Phase B: out[t][d] = resid[t][d] + sum_e act[t][e] * w2[e][d]
    for (int ch = 0; ch < 8; ch++) {
        #pragma unroll
        for (int i = 0; i < 2; i++) {
            const int fid = i * 256 + tid;
            const int row = fid >> 5, col = fid & 31;
            *(float4*)&w0s[row][col * 4] =
                *(const float4*)(experts + ((size_t)2 * kE + es[row]) * kD + ch * 128 + col * 4);
        }
        __syncthreads();
        #pragma unroll
        for (int i = 0; i < 2; i++) {
            const int d4 = ee * 2 + i;            // 0..31
            const int d  = ch * 128 + d4 * 4;
            float4 acc = *(const float4*)(resid + (size_t)(t0 + tt) * kD + d);
            #pragma unroll
            for (int e = 0; e < kET; e++) {
                const float a = act_s[tt][e];
                const float4 wv = *(const float4*)&w0s[e][d4 * 4];
                acc.x += a * wv.x; acc.y += a * wv.y;
                acc.z += a * wv.z; acc.w += a * wv.w;
            }
            *(float4*)(out + (size_t)(t0 + tt) * kD + d) = acc;
        }
        __syncthreads();
    }
}

// ---------------- launch ----------------
extern "C" void kernel_launch(void* const* d_in, const int* in_sizes, int n_in,
                              void* d_out, int out_size) {
    const float* x_input     = (const float*)d_in[0];
    const int*   indices     = (const int*)  d_in[1];
    const float* scores      = (const float*)d_in[2];
    const float* attn_w      = (const float*)d_in[3];
    const float* attn_out_w  = (const float*)d_in[4];
    const float* attn_norm_w = (const float*)d_in[5];
    const float* ffn_norm_w  = (const float*)d_in[6];
    const float* ffn_experts = (const float*)d_in[7];
    const float* keys        = (const float*)d_in[8];
    const float* head_probs  = (const float*)d_in[9];
    const float* score_probs = (const float*)d_in[10];
    float* out = (float*)d_out;

    float *qkv, *proj, *resid, *xf, *G, *wb;
    __nv_bfloat16 *xnh, *xnl, *w1h, *w1l, *w2h, *w2l, *ah, *al, *qh, *kh, *vh, *vl;
    cudaGetSymbolAddress((void**)&qkv,   g_qkv);
    cudaGetSymbolAddress((void**)&proj,  g_proj);
    cudaGetSymbolAddress((void**)&resid, g_resid);
    cudaGetSymbolAddress((void**)&xf,    g_xf);
    cudaGetSymbolAddress((void**)&G,     g_G);
    cudaGetSymbolAddress((void**)&wb,    g_w);
    cudaGetSymbolAddress((void**)&xnh,   g_xnh);
    cudaGetSymbolAddress((void**)&xnl,   g_xnl);
    cudaGetSymbolAddress((void**)&w1h,   g_w1h);
    cudaGetSymbolAddress((void**)&w1l,   g_w1l);
    cudaGetSymbolAddress((void**)&w2h,   g_w2h);
    cudaGetSymbolAddress((void**)&w2l,   g_w2l);
    cudaGetSymbolAddress((void**)&ah,    g_ah);
    cudaGetSymbolAddress((void**)&al,    g_al);
    cudaGetSymbolAddress((void**)&qh,    g_qh);
    cudaGetSymbolAddress((void**)&kh,    g_kh);
    cudaGetSymbolAddress((void**)&vh,    g_vh);
    cudaGetSymbolAddress((void**)&vl,    g_vl);

    cudaFuncSetAttribute(gemm_mma_kernel,
                         cudaFuncAttributeMaxDynamicSharedMemorySize, kGemmSmemDyn);
    cudaFuncSetAttribute(attn_kernel,
                         cudaFuncAttributeMaxDynamicSharedMemorySize, kAttnSmemDyn);

    // weight conversions (deterministic every call)
    transpose_convert_kernel<<<dim3(3 * kD / 32, kD / 32), dim3(32, 8)>>>(attn_w, w1h, w1l, kD, 3 * kD);
    transpose_convert_kernel<<<dim3(kD / 32, kD / 32), dim3(32, 8)>>>(attn_out_w, w2h, w2l, kD, kD);

    rmsnorm_bf16_kernel<<<kT, 256>>>(x_input, attn_norm_w, xnh, xnl);
    gemm_mma_kernel<<<dim3(3 * kD / 128, kT / 128), 256, kGemmSmemDyn>>>(xnh, xnl, w1h, w1l, qkv, kD, 3 * kD);
    qkprep_kernel<<<kT, 256>>>(qkv, qh, kh, vh, vl);
    attn_kernel<<<dim3(kNH, kS / 64), 128, kAttnSmemDyn>>>(qh, kh, vh, vl, ah, al);
    gemm_mma_kernel<<<dim3(kD / 128, kT / 128), 256, kGemmSmemDyn>>>(ah, al, w2h, w2l, proj, kD, kD);
    resid_rmsnorm_kernel<<<kT, 256>>>(proj, x_input, ffn_norm_w, resid, xf);
    route_gemm_kernel<<<dim3(kET, kBC), 256>>>(xf, keys, indices, G);
    combine_kernel<<<(kT * kET + 255) / 256, 256>>>(G, scores, indices, head_probs, score_probs, wb);
    expert_kernel<<<dim3(kBC, 8), 256>>>(xf, ffn_experts, indices, wb, resid, out);
}

// round 15
// speedup vs baseline: 1.0290x; 1.0242x over previous
#include <cuda_runtime.h>
#include <cuda_bf16.h>
#include <math.h>
#include <stdint.h>

// ---------------- problem constants ----------------
constexpr int kD   = 1024;
constexpr int kHD  = 64;
constexpr int kNH  = 16;
constexpr int kH   = 16;   // routing heads
constexpr int kKH  = 8;
constexpr int kN   = 128;  // tokens per block
constexpr int kE   = 4096;
constexpr int kRE  = 4;
constexpr int kDE  = 4;
constexpr int kET  = 16;   // RE*DE
constexpr int kS   = 2048;
constexpr int kT   = 2048;
constexpr int kBC  = 16;   // T / N
constexpr float kEPS   = 1e-5f;
constexpr float kTHETA = 10000.0f;

// ---------------- device scratch ----------------
__device__ float g_qkv  [kT * 3 * kD];    // qkv
__device__ float g_proj [kT * kD];        // attn out-proj
__device__ float g_resid[kT * kD];        // x_ffn_input
__device__ float g_xf   [kT * kD];        // rmsnorm(x_ffn_input)
__device__ float g_G    [kT * kET * 8];   // gathered routing dots per (t, j, h2)
__device__ float g_w    [kT * kET];       // combined gate weights
// split-bf16 buffers for tensor-core GEMMs / attention
__device__ __nv_bfloat16 g_xnh[kT * kD];          // rmsnorm(x) hi
__device__ __nv_bfloat16 g_xnl[kT * kD];          // rmsnorm(x) lo
__device__ __nv_bfloat16 g_w1h[3 * kD * kD];      // attn_w transposed [3D][D] hi
__device__ __nv_bfloat16 g_w1l[3 * kD * kD];
__device__ __nv_bfloat16 g_w2h[kD * kD];          // attn_out_w transposed hi
__device__ __nv_bfloat16 g_w2l[kD * kD];
__device__ __nv_bfloat16 g_ah [kT * kD];          // attention output hi
__device__ __nv_bfloat16 g_al [kT * kD];          // attention output lo
__device__ __nv_bfloat16 g_qh [kNH * kS * kHD];   // rope'd q bf16, (h,s,d)
__device__ __nv_bfloat16 g_kh [kNH * kS * kHD];   // rope'd k bf16
__device__ __nv_bfloat16 g_vh [kNH * kS * kHD];   // v hi, (h,s,d)
__device__ __nv_bfloat16 g_vl [kNH * kS * kHD];   // v lo

// ---------------- helpers ----------------
__device__ __forceinline__ float block_reduce_sum_256(float v) {
    __shared__ float red[8];
    #pragma unroll
    for (int o = 16; o; o >>= 1) v += __shfl_xor_sync(0xffffffffu, v, o);
    if ((threadIdx.x & 31) == 0) red[threadIdx.x >> 5] = v;
    __syncthreads();
    float s = 0.f;
    #pragma unroll
    for (int i = 0; i < 8; i++) s += red[i];
    __syncthreads();
    return s;
}

// exp(x) for |x| <= 0.13 : degree-4 Taylor, abs err ~3e-7, 4 FMA, no MUFU.
__device__ __forceinline__ float exp_small(float x) {
    float e = fmaf(x, 1.0f / 24.0f, 1.0f / 6.0f);
    e = fmaf(e, x, 0.5f);
    e = fmaf(e, x, 1.0f);
    e = fmaf(e, x, 1.0f);
    return e;
}

__device__ __forceinline__ __nv_bfloat162 split_pair(float a, float b,
                                                     __nv_bfloat162& lo) {
    __nv_bfloat16 ha = __float2bfloat16(a);
    __nv_bfloat16 hb = __float2bfloat16(b);
    lo = __nv_bfloat162(__float2bfloat16(a - __bfloat162float(ha)),
                        __float2bfloat16(b - __bfloat162float(hb)));
    return __nv_bfloat162(ha, hb);
}

__device__ __forceinline__ uint32_t smem_u32(const void* p) {
    uint32_t a;
    asm("{ .reg .u64 t; cvta.to.shared.u64 t, %1; cvt.u32.u64 %0, t; }" : "=r"(a) : "l"(p));
    return a;
}

__device__ __forceinline__ uint32_t sw128(uint32_t off) {
    return off ^ ((off >> 3) & 0x70);
}
__device__ __forceinline__ uint32_t sw64(uint32_t off) {
    return off ^ ((off >> 3) & 0x30);
}
__device__ __forceinline__ void ldsm4(uint32_t* d, uint32_t a) {
    asm volatile("ldmatrix.sync.aligned.m8n8.x4.shared.b16 {%0,%1,%2,%3}, [%4];"
        : "=r"(d[0]), "=r"(d[1]), "=r"(d[2]), "=r"(d[3]) : "r"(a));
}
__device__ __forceinline__ void ldsm4t(uint32_t* d, uint32_t a) {
    asm volatile("ldmatrix.sync.aligned.m8n8.x4.trans.shared.b16 {%0,%1,%2,%3}, [%4];"
        : "=r"(d[0]), "=r"(d[1]), "=r"(d[2]), "=r"(d[3]) : "r"(a));
}
__device__ __forceinline__ void hmma(float* d, const uint32_t* a, const uint32_t* b) {
    asm volatile("mma.sync.aligned.m16n8k16.row.col.f32.bf16.bf16.f32 "
        "{%0,%1,%2,%3}, {%4,%5,%6,%7}, {%8,%9}, {%0,%1,%2,%3};"
        : "+f"(d[0]), "+f"(d[1]), "+f"(d[2]), "+f"(d[3])
        : "r"(a[0]), "r"(a[1]), "r"(a[2]), "r"(a[3]), "r"(b[0]), "r"(b[1]));
}
__device__ __forceinline__ void cp_async16(uint32_t dst, const void* src) {
    asm volatile("cp.async.cg.shared.global [%0], [%1], 16;" :: "r"(dst), "l"(src) : "memory");
}
__device__ __forceinline__ void cp_commit() {
    asm volatile("cp.async.commit_group;" ::: "memory");
}

// ---------------- K1: rmsnorm -> split bf16 hi/lo ----------------
__global__ void rmsnorm_bf16_kernel(const float* __restrict__ x,
                                    const float* __restrict__ w,
                                    __nv_bfloat16* __restrict__ oh,
                                    __nv_bfloat16* __restrict__ ol) {
    const int t = blockIdx.x;
    const float4 v = ((const float4*)(x + t * kD))[threadIdx.x];
    float ss = v.x*v.x + v.y*v.y + v.z*v.z + v.w*v.w;
    ss = block_reduce_sum_256(ss);
    const float scale = rsqrtf(ss * (1.0f / kD) + kEPS);
    const float4 wv = ((const float4*)w)[threadIdx.x];
    const float a = v.x * scale * wv.x, b = v.y * scale * wv.y;
    const float c = v.z * scale * wv.z, d = v.w * scale * wv.w;
    __nv_bfloat162 l0, l1;
    const __nv_bfloat162 h0 = split_pair(a, b, l0);
    const __nv_bfloat162 h1 = split_pair(c, d, l1);
    ((__nv_bfloat162*)(oh + t * kD))[threadIdx.x * 2 + 0] = h0;
    ((__nv_bfloat162*)(oh + t * kD))[threadIdx.x * 2 + 1] = h1;
    ((__nv_bfloat162*)(ol + t * kD))[threadIdx.x * 2 + 0] = l0;
    ((__nv_bfloat162*)(ol + t * kD))[threadIdx.x * 2 + 1] = l1;
}

// ---------------- K1c: transpose + split convert: W[K][N] -> Bh/Bl [N][K] ----------------
__global__ void transpose_convert_kernel(const float* __restrict__ W,
                                         __nv_bfloat16* __restrict__ Bh,
                                         __nv_bfloat16* __restrict__ Bl,
                                         int K, int N) {
    __shared__ float tile[32][33];
    const int n0 = blockIdx.x * 32, k0 = blockIdx.y * 32;
    const int tx = threadIdx.x, ty = threadIdx.y;
    #pragma unroll
    for (int i = ty; i < 32; i += 8)
        tile[i][tx] = W[(size_t)(k0 + i) * N + n0 + tx];
    __syncthreads();
    #pragma unroll
    for (int i = ty; i < 32; i += 8) {
        const float v = tile[tx][i];          // k_local=tx, n_local=i
        const __nv_bfloat16 h = __float2bfloat16(v);
        Bh[(size_t)(n0 + i) * K + k0 + tx] = h;
        Bl[(size_t)(n0 + i) * K + k0 + tx] = __float2bfloat16(v - __bfloat162float(h));
    }
}

// ---------------- K2: residual add + rmsnorm ----------------
__global__ void resid_rmsnorm_kernel(const float* __restrict__ a,
                                     const float* __restrict__ b,
                                     const float* __restrict__ w,
                                     float* __restrict__ resid,
                                     float* __restrict__ xf) {
    const int t = blockIdx.x;
    const float4 va = ((const float4*)(a + t * kD))[threadIdx.x];
    const float4 vb = ((const float4*)(b + t * kD))[threadIdx.x];
    float4 v;
    v.x = va.x + vb.x; v.y = va.y + vb.y; v.z = va.z + vb.z; v.w = va.w + vb.w;
    ((float4*)(resid + t * kD))[threadIdx.x] = v;
    float ss = v.x*v.x + v.y*v.y + v.z*v.z + v.w*v.w;
    ss = block_reduce_sum_256(ss);
    const float scale = rsqrtf(ss * (1.0f / kD) + kEPS);
    const float4 wv = ((const float4*)w)[threadIdx.x];
    float4 o;
    o.x = v.x * scale * wv.x; o.y = v.y * scale * wv.y;
    o.z = v.z * scale * wv.z; o.w = v.w * scale * wv.w;
    ((float4*)(xf + t * kD))[threadIdx.x] = o;
}

// ---------------- K3: HMMA bf16 split GEMM, 64x128 CTA tile, 3-stage cp.async ----
// C[M][N] = A[M][K] * B'^T ; A = Ah+Al, B' (stored [N][K]) = Bh+Bl.
// C ~= Ah*Bh + Ah*Bl + Al*Bh. 8 warps (2x4), warp tile 32x32, BK=32.
constexpr int kATile      = 64 * 64;                 // 4KB (one A operand tile)
constexpr int kBTile      = 128 * 64;                // 8KB (one B operand tile)
constexpr int kStageBytes = 2 * kATile + 2 * kBTile; // 24KB
constexpr int kGemmStages = 3;
constexpr int kGemmSmemDyn = kGemmStages * kStageBytes;  // 72KB

__global__ __launch_bounds__(256, 2) void gemm_mma_kernel(const __nv_bfloat16* __restrict__ Ah,
                                                          const __nv_bfloat16* __restrict__ Al,
                                                          const __nv_bfloat16* __restrict__ Bh,
                                                          const __nv_bfloat16* __restrict__ Bl,
                                                          float* __restrict__ C,
                                                          int K, int N) {
    extern __shared__ __align__(128) char dynsm[];
    const uint32_t sbase = smem_u32(dynsm);
    const int tid  = threadIdx.x;
    const int wid  = tid >> 5;
    const int lane = tid & 31;
    const int wm = wid >> 2;           // 0..1 : warp row block of 32
    const int wn = wid & 3;            // 0..3 : warp col block of 32
    const int m0 = blockIdx.y * 64;
    const int n0 = blockIdx.x * 128;

    float acc[2][4][4];
    #pragma unroll
    for (int i = 0; i < 2; i++)
        #pragma unroll
        for (int j = 0; j < 4; j++)
            #pragma unroll
            for (int r = 0; r < 4; r++) acc[i][j][r] = 0.f;

    const int lr = lane & 7;
    const int lm = lane >> 3;
    const int a_row_off = ((lm & 1) << 3) + lr;
    const int a_kh      = lm >> 1;
    const int b_row_off = ((lm >> 1) << 3) + lr;
    const int b_kh      = lm & 1;

    auto load_stage = [&](int stage, int c) {
        const uint32_t sb = sbase + stage * kStageBytes;
        // A tiles: 64 rows x 4 units -> 256 cp per array, 1 per thread
        {
            const int row = tid >> 2, unit = tid & 3;
            const uint32_t so = sw64(row * 64 + unit * 16);
            const size_t ga = (size_t)(m0 + row) * K + c * 32 + unit * 8;
            cp_async16(sb + 0 * kATile + so, Ah + ga);
            cp_async16(sb + 1 * kATile + so, Al + ga);
        }
        // B tiles: 128 rows x 4 units -> 512 per array, 2 per thread
        #pragma unroll
        for (int i = 0; i < 2; i++) {
            const int idx = i * 256 + tid;
            const int row = idx >> 2, unit = idx & 3;
            const uint32_t so = sw64(row * 64 + unit * 16);
            const size_t gb = (size_t)(n0 + row) * K + c * 32 + unit * 8;
            cp_async16(sb + 2 * kATile + so, Bh + gb);
            cp_async16(sb + 2 * kATile + kBTile + so, Bl + gb);
        }
        cp_commit();
    };

    const int nchunks = K >> 5;        // K/32
    load_stage(0, 0);
    load_stage(1, 1);
    for (int c = 0; c < nchunks; c++) {
        if (c + 1 < nchunks)
            asm volatile("cp.async.wait_group 1;" ::: "memory");
        else
            asm volatile("cp.async.wait_group 0;" ::: "memory");
        __syncthreads();   // chunk c landed; all warps done computing chunk c-1
        if (c + 2 < nchunks) load_stage((c + 2) % kGemmStages, c + 2);

        const uint32_t bAh = sbase + (c % kGemmStages) * kStageBytes;
        const uint32_t bAl = bAh + kATile;
        const uint32_t bBh = bAh + 2 * kATile;
        const uint32_t bBl = bBh + kBTile;
        #pragma unroll
        for (int ks = 0; ks < 2; ks++) {
            uint32_t fah[2][4], fal[2][4], fbh[4][2], fbl[4][2];
            const int aunit = ks * 2 + a_kh;
            #pragma unroll
            for (int mt = 0; mt < 2; mt++) {
                const int row = wm * 32 + mt * 16 + a_row_off;
                const uint32_t so = sw64(row * 64 + aunit * 16);
                ldsm4(fah[mt], bAh + so);
                ldsm4(fal[mt], bAl + so);
            }
            const int bunit = ks * 2 + b_kh;
            #pragma unroll
            for (int np = 0; np < 2; np++) {
                const int row = wn * 32 + np * 16 + b_row_off;
                const uint32_t so = sw64(row * 64 + bunit * 16);
                uint32_t t4[4];
                ldsm4(t4, bBh + so);
                fbh[np * 2][0] = t4[0]; fbh[np * 2][1] = t4[1];
                fbh[np * 2 + 1][0] = t4[2]; fbh[np * 2 + 1][1] = t4[3];
                ldsm4(t4, bBl + so);
                fbl[np * 2][0] = t4[0]; fbl[np * 2][1] = t4[1];
                fbl[np * 2 + 1][0] = t4[2]; fbl[np * 2 + 1][1] = t4[3];
            }
            #pragma unroll
            for (int mt = 0; mt < 2; mt++) {
                #pragma unroll
                for (int nt = 0; nt < 4; nt++) {
                    hmma(acc[mt][nt], fah[mt], fbh[nt]);
                    hmma(acc[mt][nt], fah[mt], fbl[nt]);
                    hmma(acc[mt][nt], fal[mt], fbh[nt]);
                }
            }
        }
    }
    const int gid = lane >> 2;
    const int tig = lane & 3;
    #pragma unroll
    for (int mt = 0; mt < 2; mt++) {
        #pragma unroll
        for (int nt = 0; nt < 4; nt++) {
            const int row = m0 + wm * 32 + mt * 16 + gid;
            const int col = n0 + wn * 32 + nt * 8 + tig * 2;
            *(float2*)(C + (size_t)row * N + col) =
                make_float2(acc[mt][nt][0], acc[mt][nt][1]);
            *(float2*)(C + (size_t)(row + 8) * N + col) =
                make_float2(acc[mt][nt][2], acc[mt][nt][3]);
        }
    }
}

// ---------------- K4: l2norm + rope -> bf16 q/k; split v -> bf16 hi/lo ----------------
__global__ void qkprep_kernel(const float* __restrict__ qkv,
                              __nv_bfloat16* __restrict__ qh,
                              __nv_bfloat16* __restrict__ kh,
                              __nv_bfloat16* __restrict__ vh,
                              __nv_bfloat16* __restrict__ vl) {
    const int t = blockIdx.x;
    const int warp = threadIdx.x >> 5;
    const int lane = threadIdx.x & 31;
    const float inv_freq = powf(kTHETA, -(float)lane / 32.0f);
    const float freq = (float)t * inv_freq;
    const float c = cosf(freq), sn = sinf(freq);
    #pragma unroll
    for (int hh = 0; hh < 2; hh++) {
        const int h = warp * 2 + hh;
        const size_t hbase = ((size_t)h * kS + t) * kHD;
        #pragma unroll
        for (int qk = 0; qk < 2; qk++) {
            const float* src = qkv + t * (3 * kD) + qk * kD + h * kHD;
            float v1 = src[lane];
            float v2 = src[lane + 32];
            float ss = v1 * v1 + v2 * v2;
            #pragma unroll
            for (int o = 16; o; o >>= 1) ss += __shfl_xor_sync(0xffffffffu, ss, o);
            const float inv = 1.0f / fmaxf(sqrtf(ss), kEPS);
            v1 *= inv; v2 *= inv;
            const float o1 =  v1 * c + v2 * sn;
            const float o2 = -v1 * sn + v2 * c;
            __nv_bfloat16* dst = (qk ? kh : qh) + hbase;
            dst[lane]      = __float2bfloat16(o1);
            dst[lane + 32] = __float2bfloat16(o2);
        }
        // v split
        const float* vs = qkv + t * (3 * kD) + 2 * kD + h * kHD;
        #pragma unroll
        for (int p = 0; p < 2; p++) {
            const int d = lane + p * 32;
            const float v = vs[d];
            const __nv_bfloat16 hv = __float2bfloat16(v);
            vh[hbase + d] = hv;
            vl[hbase + d] = __float2bfloat16(v - __bfloat162float(hv));
        }
    }
}

// ---------------- K5: causal attention on HMMA (FA2-style, R12 sync version) ----------------
__global__ __launch_bounds__(128) void attn_kernel(const __nv_bfloat16* __restrict__ qg,
                                                   const __nv_bfloat16* __restrict__ kg,
                                                   const __nv_bfloat16* __restrict__ vhg,
                                                   const __nv_bfloat16* __restrict__ vlg,
                                                   __nv_bfloat16* __restrict__ ah,
                                                   __nv_bfloat16* __restrict__ al) {
    const int h  = blockIdx.x;
    const int qb = (gridDim.y - 1) - blockIdx.y;   // LPT
    const int tid = threadIdx.x;
    const int wid = tid >> 5;
    const int lane = tid & 31;
    __shared__ __align__(128) char Qs[64 * 128];
    __shared__ __align__(128) char Ks[64 * 128];
    __shared__ __align__(128) char Vhs[64 * 128];
    __shared__ __align__(128) char Vls[64 * 128];
    const uint32_t bQ = smem_u32(Qs), bK = smem_u32(Ks);
    const uint32_t bVh = smem_u32(Vhs), bVl = smem_u32(Vls);

    #pragma unroll
    for (int i = 0; i < 4; i++) {
        const int idx = i * 128 + tid;       // 0..511
        const int row = idx >> 3, unit = idx & 7;
        *(uint4*)(Qs + sw128(row * 128 + unit * 16)) =
            *(const uint4*)(qg + ((size_t)h * kS + qb * 64 + row) * kHD + unit * 8);
    }
    __syncthreads();

    const int lr = lane & 7;
    const int lm = lane >> 3;
    const int a_row = wid * 16 + ((lm & 1) << 3) + lr;
    const int a_kh  = lm >> 1;
    const int b_row = ((lm >> 1) << 3) + lr;
    const int b_kh  = lm & 1;

    uint32_t qa[4][4];
    #pragma unroll
    for (int cc = 0; cc < 4; cc++)
        ldsm4(qa[cc], bQ + sw128(a_row * 128 + (cc * 2 + a_kh) * 16));

    float oacc[8][4];
    #pragma unroll
    for (int j = 0; j < 8; j++)
        #pragma unroll
        for (int r = 0; r < 4; r++) oacc[j][r] = 0.f;
    float l0 = 0.f, l1 = 0.f;

    const int gid = lane >> 2;
    const int tig = lane & 3;
    const int qloc0 = wid * 16 + gid;
    const int ntiles = qb + 1;

    for (int kt = 0; kt < ntiles; kt++) {
        const int base = kt * 64;
        __syncthreads();
        #pragma unroll
        for (int i = 0; i < 4; i++) {
            const int idx = i * 128 + tid;
            const int row = idx >> 3, unit = idx & 7;
            const uint32_t sw = sw128(row * 128 + unit * 16);
            const size_t gi = ((size_t)h * kS + base + row) * kHD + unit * 8;
            *(uint4*)(Ks + sw)  = *(const uint4*)(kg + gi);
            *(uint4*)(Vhs + sw) = *(const uint4*)(vhg + gi);
            *(uint4*)(Vls + sw) = *(const uint4*)(vlg + gi);
        }
        __syncthreads();
        float sacc[8][4];
        #pragma unroll
        for (int j = 0; j < 8; j++)
            #pragma unroll
            for (int r = 0; r < 4; r++) sacc[j][r] = 0.f;
        #pragma unroll
        for (int cc = 0; cc < 4; cc++) {
            #pragma unroll
            for (int np = 0; np < 4; np++) {
                uint32_t t4[4];
                ldsm4(t4, bK + sw128((np * 16 + b_row) * 128 + (cc * 2 + b_kh) * 16));
                uint32_t f0[2] = {t4[0], t4[1]};
                uint32_t f1[2] = {t4[2], t4[3]};
                hmma(sacc[np * 2],     qa[cc], f0);
                hmma(sacc[np * 2 + 1], qa[cc], f1);
            }
        }
        const bool diag = (kt == qb);
        #pragma unroll
        for (int j = 0; j < 8; j++) {
            float p0 = exp_small(sacc[j][0] * 0.125f);
            float p1 = exp_small(sacc[j][1] * 0.125f);
            float p2 = exp_small(sacc[j][2] * 0.125f);
            float p3 = exp_small(sacc[j][3] * 0.125f);
            if (diag) {
                const int k0 = j * 8 + tig * 2;
                if (k0 > qloc0)     p0 = 0.f;
                if (k0 + 1 > qloc0) p1 = 0.f;
                if (k0 > qloc0 + 8)     p2 = 0.f;
                if (k0 + 1 > qloc0 + 8) p3 = 0.f;
            }
            l0 += p0 + p1;
            l1 += p2 + p3;
            sacc[j][0] = p0; sacc[j][1] = p1; sacc[j][2] = p2; sacc[j][3] = p3;
        }
        uint32_t pah[4][4], pal[4][4];
        #pragma unroll
        for (int cc = 0; cc < 4; cc++) {
            #pragma unroll
            for (int half = 0; half < 2; half++) {
                const int j = 2 * cc + half;
                __nv_bfloat162 lo01, lo23;
                const __nv_bfloat162 h01 = split_pair(sacc[j][0], sacc[j][1], lo01);
                const __nv_bfloat162 h23 = split_pair(sacc[j][2], sacc[j][3], lo23);
                pah[cc][half * 2 + 0] = *(const uint32_t*)&h01;
                pah[cc][half * 2 + 1] = *(const uint32_t*)&h23;
                pal[cc][half * 2 + 0] = *(const uint32_t*)&lo01;
                pal[cc][half * 2 + 1] = *(const uint32_t*)&lo23;
            }
        }
        #pragma unroll
        for (int cc = 0; cc < 4; cc++) {
            const int vrow = cc * 16 + ((lm & 1) << 3) + lr;
            #pragma unroll
            for (int jp = 0; jp < 4; jp++) {
                const int dunit = jp * 2 + (lm >> 1);
                uint32_t t4[4];
                ldsm4t(t4, bVh + sw128(vrow * 128 + dunit * 16));
                uint32_t f0[2] = {t4[0], t4[1]};
                uint32_t f1[2] = {t4[2], t4[3]};
                hmma(oacc[jp * 2],     pah[cc], f0);
                hmma(oacc[jp * 2 + 1], pah[cc], f1);
                hmma(oacc[jp * 2],     pal[cc], f0);
                hmma(oacc[jp * 2 + 1], pal[cc], f1);
                ldsm4t(t4, bVl + sw128(vrow * 128 + dunit * 16));
                uint32_t g0[2] = {t4[0], t4[1]};
                uint32_t g1[2] = {t4[2], t4[3]};
                hmma(oacc[jp * 2],     pah[cc], g0);
                hmma(oacc[jp * 2 + 1], pah[cc], g1);
            }
        }
    }
    l0 += __shfl_xor_sync(0xffffffffu, l0, 1);
    l0 += __shfl_xor_sync(0xffffffffu, l0, 2);
    l1 += __shfl_xor_sync(0xffffffffu, l1, 1);
    l1 += __shfl_xor_sync(0xffffffffu, l1, 2);
    const float inv0 = 1.0f / l0;
    const float inv1 = 1.0f / l1;
    const int q0 = qb * 64 + wid * 16 + gid;
    #pragma unroll
    for (int jd = 0; jd < 8; jd++) {
        const int d = h * kHD + jd * 8 + tig * 2;
        __nv_bfloat162 lo;
        __nv_bfloat162 hi = split_pair(oacc[jd][0] * inv0, oacc[jd][1] * inv0, lo);
        *(__nv_bfloat162*)(ah + (size_t)q0 * kD + d) = hi;
        *(__nv_bfloat162*)(al + (size_t)q0 * kD + d) = lo;
        hi = split_pair(oacc[jd][2] * inv1, oacc[jd][3] * inv1, lo);
        *(__nv_bfloat162*)(ah + (size_t)(q0 + 8) * kD + d) = hi;
        *(__nv_bfloat162*)(al + (size_t)(q0 + 8) * kD + d) = lo;
    }
}

// ---------------- K6: gathered routing GEMM ----------------
__global__ __launch_bounds__(256) void route_gemm_kernel(const float* __restrict__ xf,
                                                         const float* __restrict__ keys,
                                                         const int* __restrict__ indices,
                                                         float* __restrict__ G) {
    const int j = blockIdx.x;
    const int c = blockIdx.y;
    const int e = indices[c * kET + j];
    __shared__ float4 kcol[8 * 256];  // [h2][d4] : 8 heads x 1024 floats
    #pragma unroll
    for (int r = 0; r < 8; r++) {
        const int idx = r * 256 + threadIdx.x;
        const int h2 = idx >> 8;
        const int d4 = idx & 255;
        const float* base = keys + (size_t)h2 * kD * kE + (size_t)(d4 * 4) * kE + e;
        float4 v;
        v.x = __ldg(base);
        v.y = __ldg(base + kE);
        v.z = __ldg(base + 2 * kE);
        v.w = __ldg(base + 3 * kE);
        kcol[idx] = v;
    }
    __syncthreads();
    const int warp = threadIdx.x >> 5;
    const int lane = threadIdx.x & 31;
    for (int tt = 0; tt < 16; tt++) {
        const int t = c * kN + warp * 16 + tt;
        float acc[8];
        #pragma unroll
        for (int i = 0; i < 8; i++) acc[i] = 0.f;
        const float4* xp = (const float4*)(xf + t * kD);
        #pragma unroll
        for (int i = 0; i < 8; i++) {
            const float4 xv = xp[i * 32 + lane];
            #pragma unroll
            for (int h2 = 0; h2 < 8; h2++) {
                const float4 kv = kcol[h2 * 256 + i * 32 + lane];
                acc[h2] += xv.x * kv.x + xv.y * kv.y + xv.z * kv.z + xv.w * kv.w;
            }
        }
        #pragma unroll
        for (int h2 = 0; h2 < 8; h2++) {
            float s = acc[h2];
            #pragma unroll
            for (int o = 16; o; o >>= 1) s += __shfl_xor_sync(0xffffffffu, s, o);
            if (lane == 0) G[((size_t)t * kET + j) * 8 + h2] = s;
        }
    }
}

// ---------------- K7: combine gate weights ----------------
__global__ void combine_kernel(const float* __restrict__ G,
                               const float* __restrict__ scores,
                               const int* __restrict__ indices,
                               const float* __restrict__ head_probs,
                               const float* __restrict__ score_probs,
                               float* __restrict__ wbuf) {
    const int tj = blockIdx.x * blockDim.x + threadIdx.x;  // T*ET
    if (tj >= kT * kET) return;
    const int t = tj >> 4, j = tj & 15;
    const int c = t >> 7;
    const int e = indices[c * kET + j];
    const int r = j >> 2;
    const float* sp0 = score_probs + ((size_t)r * kE + e) * kH;
    const float* sp1 = score_probs + (size_t)kRE * kE * kH + ((size_t)r * kE + e) * kH;
    const float* hp = head_probs + ((size_t)r * kE + e) * kH;
    const float* sc = scores + ((size_t)t * kET + j) * kH;
    const float* g = G + (size_t)tj * 8;
    float acc = 0.f;
    #pragma unroll
    for (int h = 0; h < kH; h++) {
        const float x = sp0[h] * g[h >> 1] + sp1[h] * sc[h];
        const float sig = 1.0f / (1.0f + __expf(-x));
        acc += sig * hp[h];
    }
    wbuf[tj] = acc;
}

// ---------------- K8: expert FFN + final residual (R12 per-token version) ----------------
__global__ __launch_bounds__(256) void expert_kernel(const float* __restrict__ xf,
                                                     const float* __restrict__ experts,
                                                     const int* __restrict__ indices,
                                                     const float* __restrict__ wbuf,
                                                     const float* __restrict__ resid,
                                                     float* __restrict__ out) {
    const int t = blockIdx.x;
    const int c = t >> 7;
    __shared__ int es[kET];
    __shared__ float h01[2 * kET];
    __shared__ float act_s[kET];
    if (threadIdx.x < kET) es[threadIdx.x] = indices[c * kET + threadIdx.x];
    __syncthreads();
    const int warp = threadIdx.x >> 5;
    const int lane = threadIdx.x & 31;
    const float4* xp = (const float4*)(xf + t * kD);
    #pragma unroll
    for (int jj = 0; jj < 2; jj++) {
        const int j = warp * 2 + jj;
        const int e = es[j];
        const float4* w0 = (const float4*)(experts + ((size_t)0 * kE + e) * kD);
        const float4* w1 = (const float4*)(experts + ((size_t)1 * kE + e) * kD);
        float a0 = 0.f, a1 = 0.f;
        #pragma unroll
        for (int i = 0; i < 8; i++) {
            const float4 xv = xp[i * 32 + lane];
            const float4 v0 = w0[i * 32 + lane];
            const float4 v1 = w1[i * 32 + lane];
            a0 += xv.x * v0.x + xv.y * v0.y + xv.z * v0.z + xv.w * v0.w;
            a1 += xv.x * v1.x + xv.y * v1.y + xv.z * v1.z + xv.w * v1.w;
        }
        #pragma unroll
        for (int o = 16; o; o >>= 1) {
            a0 += __shfl_xor_sync(0xffffffffu, a0, o);
            a1 += __shfl_xor_sync(0xffffffffu, a1, o);
        }
        if (lane == 0) {
            h01[j] = a0;
            h01[kET + j] = a1;
        }
    }
    __syncthreads();
    if (threadIdx.x < kET) {
        const int j = threadIdx.x;
        const float h0 = h01[j], h1 = h01[kET + j];
        const float silu = h0 / (1.0f + __expf(-h0));
        act_s[j] = silu * h1 * wbuf[t * kET + j];
    }
    __syncthreads();
    float4 acc = ((const float4*)(resid + t * kD))[threadIdx.x];
    #pragma unroll
    for (int j = 0; j < kET; j++) {
        const float a = act_s[j];
        const float4 wv = ((const float4*)(experts + ((size_t)2 * kE + es[j]) * kD))[threadIdx.x];
        acc.x += a * wv.x; acc.y += a * wv.y; acc.z += a * wv.z; acc.w += a * wv.w;
    }
    ((float4*)(out + t * kD))[threadIdx.x] = acc;
}

// ---------------- launch ----------------
extern "C" void kernel_launch(void* const* d_in, const int* in_sizes, int n_in,
                              void* d_out, int out_size) {
    const float* x_input     = (const float*)d_in[0];
    const int*   indices     = (const int*)  d_in[1];
    const float* scores      = (const float*)d_in[2];
    const float* attn_w      = (const float*)d_in[3];
    const float* attn_out_w  = (const float*)d_in[4];
    const float* attn_norm_w = (const float*)d_in[5];
    const float* ffn_norm_w  = (const float*)d_in[6];
    const float* ffn_experts = (const float*)d_in[7];
    const float* keys        = (const float*)d_in[8];
    const float* head_probs  = (const float*)d_in[9];
    const float* score_probs = (const float*)d_in[10];
    float* out = (float*)d_out;

    float *qkv, *proj, *resid, *xf, *G, *wb;
    __nv_bfloat16 *xnh, *xnl, *w1h, *w1l, *w2h, *w2l, *ah, *al, *qh, *kh, *vh, *vl;
    cudaGetSymbolAddress((void**)&qkv,   g_qkv);
    cudaGetSymbolAddress((void**)&proj,  g_proj);
    cudaGetSymbolAddress((void**)&resid, g_resid);
    cudaGetSymbolAddress((void**)&xf,    g_xf);
    cudaGetSymbolAddress((void**)&G,     g_G);
    cudaGetSymbolAddress((void**)&wb,    g_w);
    cudaGetSymbolAddress((void**)&xnh,   g_xnh);
    cudaGetSymbolAddress((void**)&xnl,   g_xnl);
    cudaGetSymbolAddress((void**)&w1h,   g_w1h);
    cudaGetSymbolAddress((void**)&w1l,   g_w1l);
    cudaGetSymbolAddress((void**)&w2h,   g_w2h);
    cudaGetSymbolAddress((void**)&w2l,   g_w2l);
    cudaGetSymbolAddress((void**)&ah,    g_ah);
    cudaGetSymbolAddress((void**)&al,    g_al);
    cudaGetSymbolAddress((void**)&qh,    g_qh);
    cudaGetSymbolAddress((void**)&kh,    g_kh);
    cudaGetSymbolAddress((void**)&vh,    g_vh);
    cudaGetSymbolAddress((void**)&vl,    g_vl);

    cudaFuncSetAttribute(gemm_mma_kernel,
                         cudaFuncAttributeMaxDynamicSharedMemorySize, kGemmSmemDyn);

    // weight conversions (deterministic every call)
    transpose_convert_kernel<<<dim3(3 * kD / 32, kD / 32), dim3(32, 8)>>>(attn_w, w1h, w1l, kD, 3 * kD);
    transpose_convert_kernel<<<dim3(kD / 32, kD / 32), dim3(32, 8)>>>(attn_out_w, w2h, w2l, kD, kD);

    rmsnorm_bf16_kernel<<<kT, 256>>>(x_input, attn_norm_w, xnh, xnl);
    gemm_mma_kernel<<<dim3(3 * kD / 128, kT / 64), 256, kGemmSmemDyn>>>(xnh, xnl, w1h, w1l, qkv, kD, 3 * kD);
    qkprep_kernel<<<kT, 256>>>(qkv, qh, kh, vh, vl);
    attn_kernel<<<dim3(kNH, kS / 64), 128>>>(qh, kh, vh, vl, ah, al);
    gemm_mma_kernel<<<dim3(kD / 128, kT / 64), 256, kGemmSmemDyn>>>(ah, al, w2h, w2l, proj, kD, kD);
    resid_rmsnorm_kernel<<<kT, 256>>>(proj, x_input, ffn_norm_w, resid, xf);
    route_gemm_kernel<<<dim3(kET, kBC), 256>>>(xf, keys, indices, G);
    combine_kernel<<<(kT * kET + 255) / 256, 256>>>(G, scores, indices, head_probs, score_probs, wb);
    expert_kernel<<<kT, 256>>>(xf, ffn_experts, indices, wb, resid, out);
}

// round 16
// speedup vs baseline: 1.0435x; 1.0142x over previous
#include <cuda_runtime.h>
#include <cuda_bf16.h>
#include <math.h>
#include <stdint.h>

// ---------------- problem constants ----------------
constexpr int kD   = 1024;
constexpr int kHD  = 64;
constexpr int kNH  = 16;
constexpr int kH   = 16;   // routing heads
constexpr int kKH  = 8;
constexpr int kN   = 128;  // tokens per block
constexpr int kE   = 4096;
constexpr int kRE  = 4;
constexpr int kDE  = 4;
constexpr int kET  = 16;   // RE*DE
constexpr int kS   = 2048;
constexpr int kT   = 2048;
constexpr int kBC  = 16;   // T / N
constexpr float kEPS   = 1e-5f;
constexpr float kTHETA = 10000.0f;

// ---------------- device scratch ----------------
__device__ float g_qkv  [kT * 3 * kD];    // qkv
__device__ float g_proj [kT * kD];        // attn out-proj
__device__ float g_resid[kT * kD];        // x_ffn_input
__device__ float g_xf   [kT * kD];        // rmsnorm(x_ffn_input)
__device__ float g_w    [kT * kET];       // combined gate weights
// split-bf16 buffers for tensor-core GEMMs / attention
__device__ __nv_bfloat16 g_xnh[kT * kD];          // rmsnorm(x) hi
__device__ __nv_bfloat16 g_xnl[kT * kD];          // rmsnorm(x) lo
__device__ __nv_bfloat16 g_w1h[3 * kD * kD];      // attn_w transposed [3D][D] hi
__device__ __nv_bfloat16 g_w1l[3 * kD * kD];
__device__ __nv_bfloat16 g_w2h[kD * kD];          // attn_out_w transposed hi
__device__ __nv_bfloat16 g_w2l[kD * kD];
__device__ __nv_bfloat16 g_ah [kT * kD];          // attention output hi
__device__ __nv_bfloat16 g_al [kT * kD];          // attention output lo
__device__ __nv_bfloat16 g_qh [kNH * kS * kHD];   // rope'd q bf16, (h,s,d)
__device__ __nv_bfloat16 g_kh [kNH * kS * kHD];   // rope'd k bf16
__device__ __nv_bfloat16 g_vh [kNH * kS * kHD];   // v hi, (h,s,d)
__device__ __nv_bfloat16 g_vl [kNH * kS * kHD];   // v lo

// ---------------- helpers ----------------
__device__ __forceinline__ float block_reduce_sum_256(float v) {
    __shared__ float red[8];
    #pragma unroll
    for (int o = 16; o; o >>= 1) v += __shfl_xor_sync(0xffffffffu, v, o);
    if ((threadIdx.x & 31) == 0) red[threadIdx.x >> 5] = v;
    __syncthreads();
    float s = 0.f;
    #pragma unroll
    for (int i = 0; i < 8; i++) s += red[i];
    __syncthreads();
    return s;
}

// exp(x) for |x| <= 0.13 : degree-4 Taylor, abs err ~3e-7, 4 FMA, no MUFU.
__device__ __forceinline__ float exp_small(float x) {
    float e = fmaf(x, 1.0f / 24.0f, 1.0f / 6.0f);
    e = fmaf(e, x, 0.5f);
    e = fmaf(e, x, 1.0f);
    e = fmaf(e, x, 1.0f);
    return e;
}

__device__ __forceinline__ __nv_bfloat162 split_pair(float a, float b,
                                                     __nv_bfloat162& lo) {
    __nv_bfloat16 ha = __float2bfloat16(a);
    __nv_bfloat16 hb = __float2bfloat16(b);
    lo = __nv_bfloat162(__float2bfloat16(a - __bfloat162float(ha)),
                        __float2bfloat16(b - __bfloat162float(hb)));
    return __nv_bfloat162(ha, hb);
}

__device__ __forceinline__ uint32_t smem_u32(const void* p) {
    uint32_t a;
    asm("{ .reg .u64 t; cvta.to.shared.u64 t, %1; cvt.u32.u64 %0, t; }" : "=r"(a) : "l"(p));
    return a;
}

__device__ __forceinline__ uint32_t sw128(uint32_t off) {
    return off ^ ((off >> 3) & 0x70);
}
__device__ __forceinline__ uint32_t sw64(uint32_t off) {
    return off ^ ((off >> 3) & 0x30);
}
__device__ __forceinline__ void ldsm4(uint32_t* d, uint32_t a) {
    asm volatile("ldmatrix.sync.aligned.m8n8.x4.shared.b16 {%0,%1,%2,%3}, [%4];"
        : "=r"(d[0]), "=r"(d[1]), "=r"(d[2]), "=r"(d[3]) : "r"(a));
}
__device__ __forceinline__ void ldsm4t(uint32_t* d, uint32_t a) {
    asm volatile("ldmatrix.sync.aligned.m8n8.x4.trans.shared.b16 {%0,%1,%2,%3}, [%4];"
        : "=r"(d[0]), "=r"(d[1]), "=r"(d[2]), "=r"(d[3]) : "r"(a));
}
__device__ __forceinline__ void hmma(float* d, const uint32_t* a, const uint32_t* b) {
    asm volatile("mma.sync.aligned.m16n8k16.row.col.f32.bf16.bf16.f32 "
        "{%0,%1,%2,%3}, {%4,%5,%6,%7}, {%8,%9}, {%0,%1,%2,%3};"
        : "+f"(d[0]), "+f"(d[1]), "+f"(d[2]), "+f"(d[3])
        : "r"(a[0]), "r"(a[1]), "r"(a[2]), "r"(a[3]), "r"(b[0]), "r"(b[1]));
}
__device__ __forceinline__ void cp_async16(uint32_t dst, const void* src) {
    asm volatile("cp.async.cg.shared.global [%0], [%1], 16;" :: "r"(dst), "l"(src) : "memory");
}
__device__ __forceinline__ void cp_commit() {
    asm volatile("cp.async.commit_group;" ::: "memory");
}

// ---------------- K1: rmsnorm -> split bf16 hi/lo ----------------
__global__ void rmsnorm_bf16_kernel(const float* __restrict__ x,
                                    const float* __restrict__ w,
                                    __nv_bfloat16* __restrict__ oh,
                                    __nv_bfloat16* __restrict__ ol) {
    const int t = blockIdx.x;
    const float4 v = ((const float4*)(x + t * kD))[threadIdx.x];
    float ss = v.x*v.x + v.y*v.y + v.z*v.z + v.w*v.w;
    ss = block_reduce_sum_256(ss);
    const float scale = rsqrtf(ss * (1.0f / kD) + kEPS);
    const float4 wv = ((const float4*)w)[threadIdx.x];
    const float a = v.x * scale * wv.x, b = v.y * scale * wv.y;
    const float c = v.z * scale * wv.z, d = v.w * scale * wv.w;
    __nv_bfloat162 l0, l1;
    const __nv_bfloat162 h0 = split_pair(a, b, l0);
    const __nv_bfloat162 h1 = split_pair(c, d, l1);
    ((__nv_bfloat162*)(oh + t * kD))[threadIdx.x * 2 + 0] = h0;
    ((__nv_bfloat162*)(oh + t * kD))[threadIdx.x * 2 + 1] = h1;
    ((__nv_bfloat162*)(ol + t * kD))[threadIdx.x * 2 + 0] = l0;
    ((__nv_bfloat162*)(ol + t * kD))[threadIdx.x * 2 + 1] = l1;
}

// ---------------- K1c: transpose + split convert: W[K][N] -> Bh/Bl [N][K] ----------------
__global__ void transpose_convert_kernel(const float* __restrict__ W,
                                         __nv_bfloat16* __restrict__ Bh,
                                         __nv_bfloat16* __restrict__ Bl,
                                         int K, int N) {
    __shared__ float tile[32][33];
    const int n0 = blockIdx.x * 32, k0 = blockIdx.y * 32;
    const int tx = threadIdx.x, ty = threadIdx.y;
    #pragma unroll
    for (int i = ty; i < 32; i += 8)
        tile[i][tx] = W[(size_t)(k0 + i) * N + n0 + tx];
    __syncthreads();
    #pragma unroll
    for (int i = ty; i < 32; i += 8) {
        const float v = tile[tx][i];          // k_local=tx, n_local=i
        const __nv_bfloat16 h = __float2bfloat16(v);
        Bh[(size_t)(n0 + i) * K + k0 + tx] = h;
        Bl[(size_t)(n0 + i) * K + k0 + tx] = __float2bfloat16(v - __bfloat162float(h));
    }
}

// ---------------- K2: residual add + rmsnorm ----------------
__global__ void resid_rmsnorm_kernel(const float* __restrict__ a,
                                     const float* __restrict__ b,
                                     const float* __restrict__ w,
                                     float* __restrict__ resid,
                                     float* __restrict__ xf) {
    const int t = blockIdx.x;
    const float4 va = ((const float4*)(a + t * kD))[threadIdx.x];
    const float4 vb = ((const float4*)(b + t * kD))[threadIdx.x];
    float4 v;
    v.x = va.x + vb.x; v.y = va.y + vb.y; v.z = va.z + vb.z; v.w = va.w + vb.w;
    ((float4*)(resid + t * kD))[threadIdx.x] = v;
    float ss = v.x*v.x + v.y*v.y + v.z*v.z + v.w*v.w;
    ss = block_reduce_sum_256(ss);
    const float scale = rsqrtf(ss * (1.0f / kD) + kEPS);
    const float4 wv = ((const float4*)w)[threadIdx.x];
    float4 o;
    o.x = v.x * scale * wv.x; o.y = v.y * scale * wv.y;
    o.z = v.z * scale * wv.z; o.w = v.w * scale * wv.w;
    ((float4*)(xf + t * kD))[threadIdx.x] = o;
}

// ---------------- K3: HMMA bf16 split GEMM, 2-stage cp.async (R12 config) ----------
constexpr int kTileBytes  = 128 * 64;          // one operand tile, 8KB
constexpr int kStageBytes = 4 * kTileBytes;    // Ah|Al|Bh|Bl, 32KB
constexpr int kGemmSmemDyn = 2 * kStageBytes;  // 64KB

__global__ __launch_bounds__(256, 2) void gemm_mma_kernel(const __nv_bfloat16* __restrict__ Ah,
                                                          const __nv_bfloat16* __restrict__ Al,
                                                          const __nv_bfloat16* __restrict__ Bh,
                                                          const __nv_bfloat16* __restrict__ Bl,
                                                          float* __restrict__ C,
                                                          int K, int N) {
    extern __shared__ __align__(128) char dynsm[];
    const uint32_t sbase = smem_u32(dynsm);
    const int tid  = threadIdx.x;
    const int wid  = tid >> 5;
    const int lane = tid & 31;
    const int wm = wid >> 2;           // 0..1 : warp row block of 64
    const int wn = wid & 3;            // 0..3 : warp col block of 32
    const int m0 = blockIdx.y * 128;
    const int n0 = blockIdx.x * 128;

    float acc[4][4][4];
    #pragma unroll
    for (int i = 0; i < 4; i++)
        #pragma unroll
        for (int j = 0; j < 4; j++)
            #pragma unroll
            for (int r = 0; r < 4; r++) acc[i][j][r] = 0.f;

    const int lr = lane & 7;
    const int lm = lane >> 3;
    const int a_row_off = ((lm & 1) << 3) + lr;
    const int a_kh      = lm >> 1;
    const int b_row_off = ((lm >> 1) << 3) + lr;
    const int b_kh      = lm & 1;

    auto load_stage = [&](int stage, int c) {
        const uint32_t sb = sbase + stage * kStageBytes;
        #pragma unroll
        for (int i = 0; i < 2; i++) {
            const int idx  = i * 256 + tid;      // 0..511
            const int row  = idx >> 2;
            const int unit = idx & 3;
            const uint32_t so = sw64(row * 64 + unit * 16);
            const size_t ga = (size_t)(m0 + row) * K + c * 32 + unit * 8;
            const size_t gb = (size_t)(n0 + row) * K + c * 32 + unit * 8;
            cp_async16(sb + 0 * kTileBytes + so, Ah + ga);
            cp_async16(sb + 1 * kTileBytes + so, Al + ga);
            cp_async16(sb + 2 * kTileBytes + so, Bh + gb);
            cp_async16(sb + 3 * kTileBytes + so, Bl + gb);
        }
        cp_commit();
    };

    const int nchunks = K >> 5;        // K/32
    load_stage(0, 0);
    for (int c = 0; c < nchunks; c++) {
        const int cur = c & 1;
        if (c + 1 < nchunks) {
            load_stage(cur ^ 1, c + 1);
            asm volatile("cp.async.wait_group 1;" ::: "memory");
        } else {
            asm volatile("cp.async.wait_group 0;" ::: "memory");
        }
        __syncthreads();
        const uint32_t bAh = sbase + cur * kStageBytes;
        const uint32_t bAl = bAh + kTileBytes;
        const uint32_t bBh = bAh + 2 * kTileBytes;
        const uint32_t bBl = bAh + 3 * kTileBytes;
        #pragma unroll
        for (int ks = 0; ks < 2; ks++) {
            uint32_t fah[4][4], fal[4][4], fbh[4][2], fbl[4][2];
            const int aunit = ks * 2 + a_kh;
            #pragma unroll
            for (int mt = 0; mt < 4; mt++) {
                const int row = wm * 64 + mt * 16 + a_row_off;
                const uint32_t so = sw64(row * 64 + aunit * 16);
                ldsm4(fah[mt], bAh + so);
                ldsm4(fal[mt], bAl + so);
            }
            const int bunit = ks * 2 + b_kh;
            #pragma unroll
            for (int np = 0; np < 2; np++) {
                const int row = wn * 32 + np * 16 + b_row_off;
                const uint32_t so = sw64(row * 64 + bunit * 16);
                uint32_t t4[4];
                ldsm4(t4, bBh + so);
                fbh[np * 2][0] = t4[0]; fbh[np * 2][1] = t4[1];
                fbh[np * 2 + 1][0] = t4[2]; fbh[np * 2 + 1][1] = t4[3];
                ldsm4(t4, bBl + so);
                fbl[np * 2][0] = t4[0]; fbl[np * 2][1] = t4[1];
                fbl[np * 2 + 1][0] = t4[2]; fbl[np * 2 + 1][1] = t4[3];
            }
            #pragma unroll
            for (int mt = 0; mt < 4; mt++) {
                #pragma unroll
                for (int nt = 0; nt < 4; nt++) {
                    hmma(acc[mt][nt], fah[mt], fbh[nt]);
                    hmma(acc[mt][nt], fah[mt], fbl[nt]);
                    hmma(acc[mt][nt], fal[mt], fbh[nt]);
                }
            }
        }
        __syncthreads();   // all reads of buffer `cur` done before it is reloaded
    }
    const int gid = lane >> 2;
    const int tig = lane & 3;
    #pragma unroll
    for (int mt = 0; mt < 4; mt++) {
        #pragma unroll
        for (int nt = 0; nt < 4; nt++) {
            const int row = m0 + wm * 64 + mt * 16 + gid;
            const int col = n0 + wn * 32 + nt * 8 + tig * 2;
            *(float2*)(C + (size_t)row * N + col) =
                make_float2(acc[mt][nt][0], acc[mt][nt][1]);
            *(float2*)(C + (size_t)(row + 8) * N + col) =
                make_float2(acc[mt][nt][2], acc[mt][nt][3]);
        }
    }
}

// ---------------- K4: l2norm + rope -> bf16 q/k; split v -> bf16 hi/lo ----------------
__global__ void qkprep_kernel(const float* __restrict__ qkv,
                              __nv_bfloat16* __restrict__ qh,
                              __nv_bfloat16* __restrict__ kh,
                              __nv_bfloat16* __restrict__ vh,
                              __nv_bfloat16* __restrict__ vl) {
    const int t = blockIdx.x;
    const int warp = threadIdx.x >> 5;
    const int lane = threadIdx.x & 31;
    const float inv_freq = powf(kTHETA, -(float)lane / 32.0f);
    const float freq = (float)t * inv_freq;
    const float c = cosf(freq), sn = sinf(freq);
    #pragma unroll
    for (int hh = 0; hh < 2; hh++) {
        const int h = warp * 2 + hh;
        const size_t hbase = ((size_t)h * kS + t) * kHD;
        #pragma unroll
        for (int qk = 0; qk < 2; qk++) {
            const float* src = qkv + t * (3 * kD) + qk * kD + h * kHD;
            float v1 = src[lane];
            float v2 = src[lane + 32];
            float ss = v1 * v1 + v2 * v2;
            #pragma unroll
            for (int o = 16; o; o >>= 1) ss += __shfl_xor_sync(0xffffffffu, ss, o);
            const float inv = 1.0f / fmaxf(sqrtf(ss), kEPS);
            v1 *= inv; v2 *= inv;
            const float o1 =  v1 * c + v2 * sn;
            const float o2 = -v1 * sn + v2 * c;
            __nv_bfloat16* dst = (qk ? kh : qh) + hbase;
            dst[lane]      = __float2bfloat16(o1);
            dst[lane + 32] = __float2bfloat16(o2);
        }
        // v split
        const float* vs = qkv + t * (3 * kD) + 2 * kD + h * kHD;
        #pragma unroll
        for (int p = 0; p < 2; p++) {
            const int d = lane + p * 32;
            const float v = vs[d];
            const __nv_bfloat16 hv = __float2bfloat16(v);
            vh[hbase + d] = hv;
            vl[hbase + d] = __float2bfloat16(v - __bfloat162float(hv));
        }
    }
}

// ---------------- K5: causal attention on HMMA (FA2-style, R12 version) ----------------
__global__ __launch_bounds__(128) void attn_kernel(const __nv_bfloat16* __restrict__ qg,
                                                   const __nv_bfloat16* __restrict__ kg,
                                                   const __nv_bfloat16* __restrict__ vhg,
                                                   const __nv_bfloat16* __restrict__ vlg,
                                                   __nv_bfloat16* __restrict__ ah,
                                                   __nv_bfloat16* __restrict__ al) {
    const int h  = blockIdx.x;
    const int qb = (gridDim.y - 1) - blockIdx.y;   // LPT
    const int tid = threadIdx.x;
    const int wid = tid >> 5;
    const int lane = tid & 31;
    __shared__ __align__(128) char Qs[64 * 128];
    __shared__ __align__(128) char Ks[64 * 128];
    __shared__ __align__(128) char Vhs[64 * 128];
    __shared__ __align__(128) char Vls[64 * 128];
    const uint32_t bQ = smem_u32(Qs), bK = smem_u32(Ks);
    const uint32_t bVh = smem_u32(Vhs), bVl = smem_u32(Vls);

    #pragma unroll
    for (int i = 0; i < 4; i++) {
        const int idx = i * 128 + tid;       // 0..511
        const int row = idx >> 3, unit = idx & 7;
        *(uint4*)(Qs + sw128(row * 128 + unit * 16)) =
            *(const uint4*)(qg + ((size_t)h * kS + qb * 64 + row) * kHD + unit * 8);
    }
    __syncthreads();

    const int lr = lane & 7;
    const int lm = lane >> 3;
    const int a_row = wid * 16 + ((lm & 1) << 3) + lr;
    const int a_kh  = lm >> 1;
    const int b_row = ((lm >> 1) << 3) + lr;
    const int b_kh  = lm & 1;

    uint32_t qa[4][4];
    #pragma unroll
    for (int cc = 0; cc < 4; cc++)
        ldsm4(qa[cc], bQ + sw128(a_row * 128 + (cc * 2 + a_kh) * 16));

    float oacc[8][4];
    #pragma unroll
    for (int j = 0; j < 8; j++)
        #pragma unroll
        for (int r = 0; r < 4; r++) oacc[j][r] = 0.f;
    float l0 = 0.f, l1 = 0.f;

    const int gid = lane >> 2;
    const int tig = lane & 3;
    const int qloc0 = wid * 16 + gid;
    const int ntiles = qb + 1;

    for (int kt = 0; kt < ntiles; kt++) {
        const int base = kt * 64;
        __syncthreads();
        #pragma unroll
        for (int i = 0; i < 4; i++) {
            const int idx = i * 128 + tid;
            const int row = idx >> 3, unit = idx & 7;
            const uint32_t sw = sw128(row * 128 + unit * 16);
            const size_t gi = ((size_t)h * kS + base + row) * kHD + unit * 8;
            *(uint4*)(Ks + sw)  = *(const uint4*)(kg + gi);
            *(uint4*)(Vhs + sw) = *(const uint4*)(vhg + gi);
            *(uint4*)(Vls + sw) = *(const uint4*)(vlg + gi);
        }
        __syncthreads();
        float sacc[8][4];
        #pragma unroll
        for (int j = 0; j < 8; j++)
            #pragma unroll
            for (int r = 0; r < 4; r++) sacc[j][r] = 0.f;
        #pragma unroll
        for (int cc = 0; cc < 4; cc++) {
            #pragma unroll
            for (int np = 0; np < 4; np++) {
                uint32_t t4[4];
                ldsm4(t4, bK + sw128((np * 16 + b_row) * 128 + (cc * 2 + b_kh) * 16));
                uint32_t f0[2] = {t4[0], t4[1]};
                uint32_t f1[2] = {t4[2], t4[3]};
                hmma(sacc[np * 2],     qa[cc], f0);
                hmma(sacc[np * 2 + 1], qa[cc], f1);
            }
        }
        const bool diag = (kt == qb);
        #pragma unroll
        for (int j = 0; j < 8; j++) {
            float p0 = exp_small(sacc[j][0] * 0.125f);
            float p1 = exp_small(sacc[j][1] * 0.125f);
            float p2 = exp_small(sacc[j][2] * 0.125f);
            float p3 = exp_small(sacc[j][3] * 0.125f);
            if (diag) {
                const int k0 = j * 8 + tig * 2;
                if (k0 > qloc0)     p0 = 0.f;
                if (k0 + 1 > qloc0) p1 = 0.f;
                if (k0 > qloc0 + 8)     p2 = 0.f;
                if (k0 + 1 > qloc0 + 8) p3 = 0.f;
            }
            l0 += p0 + p1;
            l1 += p2 + p3;
            sacc[j][0] = p0; sacc[j][1] = p1; sacc[j][2] = p2; sacc[j][3] = p3;
        }
        uint32_t pah[4][4], pal[4][4];
        #pragma unroll
        for (int cc = 0; cc < 4; cc++) {
            #pragma unroll
            for (int half = 0; half < 2; half++) {
                const int j = 2 * cc + half;
                __nv_bfloat162 lo01, lo23;
                const __nv_bfloat162 h01 = split_pair(sacc[j][0], sacc[j][1], lo01);
                const __nv_bfloat162 h23 = split_pair(sacc[j][2], sacc[j][3], lo23);
                pah[cc][half * 2 + 0] = *(const uint32_t*)&h01;
                pah[cc][half * 2 + 1] = *(const uint32_t*)&h23;
                pal[cc][half * 2 + 0] = *(const uint32_t*)&lo01;
                pal[cc][half * 2 + 1] = *(const uint32_t*)&lo23;
            }
        }
        #pragma unroll
        for (int cc = 0; cc < 4; cc++) {
            const int vrow = cc * 16 + ((lm & 1) << 3) + lr;
            #pragma unroll
            for (int jp = 0; jp < 4; jp++) {
                const int dunit = jp * 2 + (lm >> 1);
                uint32_t t4[4];
                ldsm4t(t4, bVh + sw128(vrow * 128 + dunit * 16));
                uint32_t f0[2] = {t4[0], t4[1]};
                uint32_t f1[2] = {t4[2], t4[3]};
                hmma(oacc[jp * 2],     pah[cc], f0);
                hmma(oacc[jp * 2 + 1], pah[cc], f1);
                hmma(oacc[jp * 2],     pal[cc], f0);
                hmma(oacc[jp * 2 + 1], pal[cc], f1);
                ldsm4t(t4, bVl + sw128(vrow * 128 + dunit * 16));
                uint32_t g0[2] = {t4[0], t4[1]};
                uint32_t g1[2] = {t4[2], t4[3]};
                hmma(oacc[jp * 2],     pah[cc], g0);
                hmma(oacc[jp * 2 + 1], pah[cc], g1);
            }
        }
    }
    l0 += __shfl_xor_sync(0xffffffffu, l0, 1);
    l0 += __shfl_xor_sync(0xffffffffu, l0, 2);
    l1 += __shfl_xor_sync(0xffffffffu, l1, 1);
    l1 += __shfl_xor_sync(0xffffffffu, l1, 2);
    const float inv0 = 1.0f / l0;
    const float inv1 = 1.0f / l1;
    const int q0 = qb * 64 + wid * 16 + gid;
    #pragma unroll
    for (int jd = 0; jd < 8; jd++) {
        const int d = h * kHD + jd * 8 + tig * 2;
        __nv_bfloat162 lo;
        __nv_bfloat162 hi = split_pair(oacc[jd][0] * inv0, oacc[jd][1] * inv0, lo);
        *(__nv_bfloat162*)(ah + (size_t)q0 * kD + d) = hi;
        *(__nv_bfloat162*)(al + (size_t)q0 * kD + d) = lo;
        hi = split_pair(oacc[jd][2] * inv1, oacc[jd][3] * inv1, lo);
        *(__nv_bfloat162*)(ah + (size_t)(q0 + 8) * kD + d) = hi;
        *(__nv_bfloat162*)(al + (size_t)(q0 + 8) * kD + d) = lo;
    }
}

// ---------------- K6: gathered routing GEMM + gate combine (fused) ----------------
// block per (j, c). Computes G[t,j,h2] via warp reduce (butterfly leaves the
// sum in ALL lanes), then lanes 0..15 evaluate the 16 routing-head sigmoid
// terms and reduce -> wbuf[t*kET+j]. No intermediate G buffer.
__global__ __launch_bounds__(256) void route_combine_kernel(const float* __restrict__ xf,
                                                            const float* __restrict__ keys,
                                                            const int* __restrict__ indices,
                                                            const float* __restrict__ scores,
                                                            const float* __restrict__ head_probs,
                                                            const float* __restrict__ score_probs,
                                                            float* __restrict__ wbuf) {
    const int j = blockIdx.x;
    const int c = blockIdx.y;
    const int e = indices[c * kET + j];
    const int r = j >> 2;
    __shared__ float4 kcol[8 * 256];  // [h2][d4] : 8 heads x 1024 floats
    __shared__ float sp0s[kH], sp1s[kH], hps[kH];
    if (threadIdx.x < kH) {
        const int h = threadIdx.x;
        sp0s[h] = score_probs[((size_t)r * kE + e) * kH + h];
        sp1s[h] = score_probs[(size_t)kRE * kE * kH + ((size_t)r * kE + e) * kH + h];
        hps[h]  = head_probs[((size_t)r * kE + e) * kH + h];
    }
    #pragma unroll
    for (int rr = 0; rr < 8; rr++) {
        const int idx = rr * 256 + threadIdx.x;
        const int h2 = idx >> 8;
        const int d4 = idx & 255;
        const float* base = keys + (size_t)h2 * kD * kE + (size_t)(d4 * 4) * kE + e;
        float4 v;
        v.x = __ldg(base);
        v.y = __ldg(base + kE);
        v.z = __ldg(base + 2 * kE);
        v.w = __ldg(base + 3 * kE);
        kcol[idx] = v;
    }
    __syncthreads();
    const int warp = threadIdx.x >> 5;
    const int lane = threadIdx.x & 31;
    for (int tt = 0; tt < 16; tt++) {
        const int t = c * kN + warp * 16 + tt;
        float acc[8];
        #pragma unroll
        for (int i = 0; i < 8; i++) acc[i] = 0.f;
        const float4* xp = (const float4*)(xf + t * kD);
        #pragma unroll
        for (int i = 0; i < 8; i++) {
            const float4 xv = xp[i * 32 + lane];
            #pragma unroll
            for (int h2 = 0; h2 < 8; h2++) {
                const float4 kv = kcol[h2 * 256 + i * 32 + lane];
                acc[h2] += xv.x * kv.x + xv.y * kv.y + xv.z * kv.z + xv.w * kv.w;
            }
        }
        #pragma unroll
        for (int h2 = 0; h2 < 8; h2++) {
            #pragma unroll
            for (int o = 16; o; o >>= 1)
                acc[h2] += __shfl_xor_sync(0xffffffffu, acc[h2], o);
        }
        // lanes 0..15: one routing head each
        const int hh = lane & 15;
        const float x = sp0s[hh] * acc[hh >> 1]
                      + sp1s[hh] * scores[((size_t)t * kET + j) * kH + hh];
        float y = hps[hh] / (1.0f + __expf(-x));
        y += __shfl_xor_sync(0xffffffffu, y, 1);
        y += __shfl_xor_sync(0xffffffffu, y, 2);
        y += __shfl_xor_sync(0xffffffffu, y, 4);
        y += __shfl_xor_sync(0xffffffffu, y, 8);
        if (lane == 0) wbuf[(size_t)t * kET + j] = y;
    }
}

// ---------------- K8: expert FFN + final residual (R12 per-token version) ----------------
__global__ __launch_bounds__(256) void expert_kernel(const float* __restrict__ xf,
                                                     const float* __restrict__ experts,
                                                     const int* __restrict__ indices,
                                                     const float* __restrict__ wbuf,
                                                     const float* __restrict__ resid,
                                                     float* __restrict__ out) {
    const int t = blockIdx.x;
    const int c = t >> 7;
    __shared__ int es[kET];
    __shared__ float h01[2 * kET];
    __shared__ float act_s[kET];
    if (threadIdx.x < kET) es[threadIdx.x] = indices[c * kET + threadIdx.x];
    __syncthreads();
    const int warp = threadIdx.x >> 5;
    const int lane = threadIdx.x & 31;
    const float4* xp = (const float4*)(xf + t * kD);
    #pragma unroll
    for (int jj = 0; jj < 2; jj++) {
        const int j = warp * 2 + jj;
        const int e = es[j];
        const float4* w0 = (const float4*)(experts + ((size_t)0 * kE + e) * kD);
        const float4* w1 = (const float4*)(experts + ((size_t)1 * kE + e) * kD);
        float a0 = 0.f, a1 = 0.f;
        #pragma unroll
        for (int i = 0; i < 8; i++) {
            const float4 xv = xp[i * 32 + lane];
            const float4 v0 = w0[i * 32 + lane];
            const float4 v1 = w1[i * 32 + lane];
            a0 += xv.x * v0.x + xv.y * v0.y + xv.z * v0.z + xv.w * v0.w;
            a1 += xv.x * v1.x + xv.y * v1.y + xv.z * v1.z + xv.w * v1.w;
        }
        #pragma unroll
        for (int o = 16; o; o >>= 1) {
            a0 += __shfl_xor_sync(0xffffffffu, a0, o);
            a1 += __shfl_xor_sync(0xffffffffu, a1, o);
        }
        if (lane == 0) {
            h01[j] = a0;
            h01[kET + j] = a1;
        }
    }
    __syncthreads();
    if (threadIdx.x < kET) {
        const int j = threadIdx.x;
        const float h0 = h01[j], h1 = h01[kET + j];
        const float silu = h0 / (1.0f + __expf(-h0));
        act_s[j] = silu * h1 * wbuf[t * kET + j];
    }
    __syncthreads();
    float4 acc = ((const float4*)(resid + t * kD))[threadIdx.x];
    #pragma unroll
    for (int j = 0; j < kET; j++) {
        const float a = act_s[j];
        const float4 wv = ((const float4*)(experts + ((size_t)2 * kE + es[j]) * kD))[threadIdx.x];
        acc.x += a * wv.x; acc.y += a * wv.y; acc.z += a * wv.z; acc.w += a * wv.w;
    }
    ((float4*)(out + t * kD))[threadIdx.x] = acc;
}

// ---------------- launch ----------------
extern "C" void kernel_launch(void* const* d_in, const int* in_sizes, int n_in,
                              void* d_out, int out_size) {
    const float* x_input     = (const float*)d_in[0];
    const int*   indices     = (const int*)  d_in[1];
    const float* scores      = (const float*)d_in[2];
    const float* attn_w      = (const float*)d_in[3];
    const float* attn_out_w  = (const float*)d_in[4];
    const float* attn_norm_w = (const float*)d_in[5];
    const float* ffn_norm_w  = (const float*)d_in[6];
    const float* ffn_experts = (const float*)d_in[7];
    const float* keys        = (const float*)d_in[8];
    const float* head_probs  = (const float*)d_in[9];
    const float* score_probs = (const float*)d_in[10];
    float* out = (float*)d_out;

    float *qkv, *proj, *resid, *xf, *wb;
    __nv_bfloat16 *xnh, *xnl, *w1h, *w1l, *w2h, *w2l, *ah, *al, *qh, *kh, *vh, *vl;
    cudaGetSymbolAddress((void**)&qkv,   g_qkv);
    cudaGetSymbolAddress((void**)&proj,  g_proj);
    cudaGetSymbolAddress((void**)&resid, g_resid);
    cudaGetSymbolAddress((void**)&xf,    g_xf);
    cudaGetSymbolAddress((void**)&wb,    g_w);
    cudaGetSymbolAddress((void**)&xnh,   g_xnh);
    cudaGetSymbolAddress((void**)&xnl,   g_xnl);
    cudaGetSymbolAddress((void**)&w1h,   g_w1h);
    cudaGetSymbolAddress((void**)&w1l,   g_w1l);
    cudaGetSymbolAddress((void**)&w2h,   g_w2h);
    cudaGetSymbolAddress((void**)&w2l,   g_w2l);
    cudaGetSymbolAddress((void**)&ah,    g_ah);
    cudaGetSymbolAddress((void**)&al,    g_al);
    cudaGetSymbolAddress((void**)&qh,    g_qh);
    cudaGetSymbolAddress((void**)&kh,    g_kh);
    cudaGetSymbolAddress((void**)&vh,    g_vh);
    cudaGetSymbolAddress((void**)&vl,    g_vl);

    cudaFuncSetAttribute(gemm_mma_kernel,
                         cudaFuncAttributeMaxDynamicSharedMemorySize, kGemmSmemDyn);

    // weight conversions (deterministic every call)
    transpose_convert_kernel<<<dim3(3 * kD / 32, kD / 32), dim3(32, 8)>>>(attn_w, w1h, w1l, kD, 3 * kD);
    transpose_convert_kernel<<<dim3(kD / 32, kD / 32), dim3(32, 8)>>>(attn_out_w, w2h, w2l, kD, kD);

    rmsnorm_bf16_kernel<<<kT, 256>>>(x_input, attn_norm_w, xnh, xnl);
    gemm_mma_kernel<<<dim3(3 * kD / 128, kT / 128), 256, kGemmSmemDyn>>>(xnh, xnl, w1h, w1l, qkv, kD, 3 * kD);
    qkprep_kernel<<<kT, 256>>>(qkv, qh, kh, vh, vl);
    attn_kernel<<<dim3(kNH, kS / 64), 128>>>(qh, kh, vh, vl, ah, al);
    gemm_mma_kernel<<<dim3(kD / 128, kT / 128), 256, kGemmSmemDyn>>>(ah, al, w2h, w2l, proj, kD, kD);
    resid_rmsnorm_kernel<<<kT, 256>>>(proj, x_input, ffn_norm_w, resid, xf);
    route_combine_kernel<<<dim3(kET, kBC), 256>>>(xf, keys, indices, scores, head_probs, score_probs, wb);
    expert_kernel<<<kT, 256>>>(xf, ffn_experts, indices, wb, resid, out);
}